// round 1
// baseline (speedup 1.0000x reference)
#include <cuda_runtime.h>
#include <cuda_bf16.h>
#include <math.h>

// Problem constants
#define Bb 256
#define Tt 256
#define Cc 384
#define Hh 64

// Scratch for Q, K, V projections ([B*T, H] each, fp32)
__device__ float g_q[Bb * Tt * Hh];
__device__ float g_k[Bb * Tt * Hh];
__device__ float g_v[Bb * Tt * Hh];

// ---------------------------------------------------------------------------
// Kernel 1: fused QKV projection.
//   grid = (1024, 3): blockIdx.x = 64-row tile of the 65536 rows,
//                     blockIdx.y = which matrix (0:Q, 1:K, 2:V)
//   block = 256 threads, each computes a 4x4 micro-tile of the 64x64 output.
// ---------------------------------------------------------------------------
__global__ __launch_bounds__(256) void qkv_kernel(
    const float* __restrict__ x,
    const float* __restrict__ Wq,
    const float* __restrict__ Wk,
    const float* __restrict__ Wv)
{
    const float* W = (blockIdx.y == 0) ? Wq : (blockIdx.y == 1) ? Wk : Wv;
    float* out     = (blockIdx.y == 0) ? g_q : (blockIdx.y == 1) ? g_k : g_v;

    __shared__ float xs[64][33];   // 64 rows x 32 k, padded
    __shared__ float ws[32][64];   // 32 k x 64 cols (float4-aligned rows)

    const int tid = threadIdx.x;
    const int tx  = tid & 15;      // col group (4 cols each)
    const int ty  = tid >> 4;      // row group (4 rows each)
    const int row0 = blockIdx.x * 64;

    float acc[4][4] = {};

    for (int kk = 0; kk < Cc; kk += 32) {
        // Load x tile: 64x32, coalesced (each warp = one row of 32)
        #pragma unroll
        for (int t = 0; t < 8; t++) {
            int i = tid + t * 256;
            int r = i >> 5, c = i & 31;
            xs[r][c] = x[(size_t)(row0 + r) * Cc + kk + c];
        }
        // Load W tile: 32x64, coalesced
        #pragma unroll
        for (int t = 0; t < 8; t++) {
            int i = tid + t * 256;
            int r = i >> 6, c = i & 63;
            ws[r][c] = W[(size_t)(kk + r) * Hh + c];
        }
        __syncthreads();

        #pragma unroll
        for (int k = 0; k < 32; k++) {
            float a0 = xs[ty * 4 + 0][k];
            float a1 = xs[ty * 4 + 1][k];
            float a2 = xs[ty * 4 + 2][k];
            float a3 = xs[ty * 4 + 3][k];
            float4 bv = *(const float4*)&ws[k][tx * 4];
            acc[0][0] += a0 * bv.x; acc[0][1] += a0 * bv.y; acc[0][2] += a0 * bv.z; acc[0][3] += a0 * bv.w;
            acc[1][0] += a1 * bv.x; acc[1][1] += a1 * bv.y; acc[1][2] += a1 * bv.z; acc[1][3] += a1 * bv.w;
            acc[2][0] += a2 * bv.x; acc[2][1] += a2 * bv.y; acc[2][2] += a2 * bv.z; acc[2][3] += a2 * bv.w;
            acc[3][0] += a3 * bv.x; acc[3][1] += a3 * bv.y; acc[3][2] += a3 * bv.z; acc[3][3] += a3 * bv.w;
        }
        __syncthreads();
    }

    #pragma unroll
    for (int i = 0; i < 4; i++) {
        float4 v = make_float4(acc[i][0], acc[i][1], acc[i][2], acc[i][3]);
        *(float4*)&out[(size_t)(row0 + ty * 4 + i) * Hh + tx * 4] = v;
    }
}

// ---------------------------------------------------------------------------
// Kernel 2: causal attention over one (batch, 64-query-row) tile.
//   grid = (4, 256): blockIdx.x = query tile (64 rows), blockIdx.y = batch.
//   Full S strip [64 x 256] in dynamic smem; softmax in-place; then P*V.
// Dynamic smem layout (floats):
//   Qs : 64*68
//   KVs: 64*68      (K^T during S phase, V during O phase)
//   Ss : 64*260     (scores / probabilities)
// ---------------------------------------------------------------------------
#define QS_STRIDE 68
#define SS_STRIDE 260

__global__ __launch_bounds__(256) void attn_kernel(float* __restrict__ out)
{
    extern __shared__ float smem[];
    float* Qs  = smem;                    // 64*68
    float* KVs = Qs + 64 * QS_STRIDE;     // 64*68
    float* Ss  = KVs + 64 * QS_STRIDE;    // 64*260

    const int tid = threadIdx.x;
    const int tx  = tid & 15;
    const int ty  = tid >> 4;
    const int qt  = blockIdx.x;           // query tile index (0..3)
    const int b   = blockIdx.y;
    const int q0  = qt * 64;
    const float scale = rsqrtf((float)Cc);   // NOTE: C**-0.5 per reference

    // Load Q tile [64 rows x 64 h]
    #pragma unroll
    for (int t = 0; t < 16; t++) {
        int i = tid + t * 256;
        int r = i >> 6, c = i & 63;
        Qs[r * QS_STRIDE + c] = g_q[(size_t)(b * Tt + q0 + r) * Hh + c];
    }
    __syncthreads();

    // ---- S = scale * Q K^T with causal mask, stored to Ss ----
    for (int jt = 0; jt <= qt; jt++) {
        // Load K tile transposed: KVs[h][t_local]
        #pragma unroll
        for (int t = 0; t < 16; t++) {
            int i = tid + t * 256;
            int r = i >> 6, c = i & 63;             // r = key row, c = h
            KVs[c * QS_STRIDE + r] = g_k[(size_t)(b * Tt + jt * 64 + r) * Hh + c];
        }
        __syncthreads();

        float acc[4][4] = {};
        #pragma unroll
        for (int k = 0; k < 64; k++) {
            float a0 = Qs[(ty * 4 + 0) * QS_STRIDE + k];
            float a1 = Qs[(ty * 4 + 1) * QS_STRIDE + k];
            float a2 = Qs[(ty * 4 + 2) * QS_STRIDE + k];
            float a3 = Qs[(ty * 4 + 3) * QS_STRIDE + k];
            float4 bv = *(const float4*)&KVs[k * QS_STRIDE + tx * 4];
            acc[0][0] += a0 * bv.x; acc[0][1] += a0 * bv.y; acc[0][2] += a0 * bv.z; acc[0][3] += a0 * bv.w;
            acc[1][0] += a1 * bv.x; acc[1][1] += a1 * bv.y; acc[1][2] += a1 * bv.z; acc[1][3] += a1 * bv.w;
            acc[2][0] += a2 * bv.x; acc[2][1] += a2 * bv.y; acc[2][2] += a2 * bv.z; acc[2][3] += a2 * bv.w;
            acc[3][0] += a3 * bv.x; acc[3][1] += a3 * bv.y; acc[3][2] += a3 * bv.z; acc[3][3] += a3 * bv.w;
        }

        // Mask + scale + store
        #pragma unroll
        for (int i = 0; i < 4; i++) {
            int qg = q0 + ty * 4 + i;
            #pragma unroll
            for (int j = 0; j < 4; j++) {
                int kg = jt * 64 + tx * 4 + j;
                float s = (kg <= qg) ? acc[i][j] * scale : -1e30f;
                Ss[(ty * 4 + i) * SS_STRIDE + jt * 64 + tx * 4 + j] = s;
            }
        }
        __syncthreads();   // KVs reused next iteration / by softmax ordering
    }

    // ---- softmax over valid columns (ncol = (qt+1)*64), 4 lanes per row ----
    {
        const int ncol = (qt + 1) * 64;
        const int row  = tid >> 2;
        const int sub  = tid & 3;
        float* rowp = &Ss[row * SS_STRIDE];

        float m = -1e30f;
        for (int c = sub; c < ncol; c += 4) m = fmaxf(m, rowp[c]);
        m = fmaxf(m, __shfl_xor_sync(0xffffffffu, m, 1));
        m = fmaxf(m, __shfl_xor_sync(0xffffffffu, m, 2));

        float s = 0.f;
        for (int c = sub; c < ncol; c += 4) {
            float e = __expf(rowp[c] - m);
            rowp[c] = e;
            s += e;
        }
        s += __shfl_xor_sync(0xffffffffu, s, 1);
        s += __shfl_xor_sync(0xffffffffu, s, 2);
        float inv = 1.f / s;
        for (int c = sub; c < ncol; c += 4) rowp[c] *= inv;
    }
    __syncthreads();

    // ---- O = P V ----
    float o[4][4] = {};
    for (int jt = 0; jt <= qt; jt++) {
        // Load V tile [64 keys x 64 h], direct layout
        #pragma unroll
        for (int t = 0; t < 16; t++) {
            int i = tid + t * 256;
            int r = i >> 6, c = i & 63;
            KVs[r * QS_STRIDE + c] = g_v[(size_t)(b * Tt + jt * 64 + r) * Hh + c];
        }
        __syncthreads();

        #pragma unroll
        for (int k = 0; k < 64; k++) {
            float a0 = Ss[(ty * 4 + 0) * SS_STRIDE + jt * 64 + k];
            float a1 = Ss[(ty * 4 + 1) * SS_STRIDE + jt * 64 + k];
            float a2 = Ss[(ty * 4 + 2) * SS_STRIDE + jt * 64 + k];
            float a3 = Ss[(ty * 4 + 3) * SS_STRIDE + jt * 64 + k];
            float4 bv = *(const float4*)&KVs[k * QS_STRIDE + tx * 4];
            o[0][0] += a0 * bv.x; o[0][1] += a0 * bv.y; o[0][2] += a0 * bv.z; o[0][3] += a0 * bv.w;
            o[1][0] += a1 * bv.x; o[1][1] += a1 * bv.y; o[1][2] += a1 * bv.z; o[1][3] += a1 * bv.w;
            o[2][0] += a2 * bv.x; o[2][1] += a2 * bv.y; o[2][2] += a2 * bv.z; o[2][3] += a2 * bv.w;
            o[3][0] += a3 * bv.x; o[3][1] += a3 * bv.y; o[3][2] += a3 * bv.z; o[3][3] += a3 * bv.w;
        }
        __syncthreads();
    }

    // Write output [B, T, H] fp32
    #pragma unroll
    for (int i = 0; i < 4; i++) {
        float4 v = make_float4(o[i][0], o[i][1], o[i][2], o[i][3]);
        *(float4*)&out[(size_t)(b * Tt + q0 + ty * 4 + i) * Hh + tx * 4] = v;
    }
}

// ---------------------------------------------------------------------------
extern "C" void kernel_launch(void* const* d_in, const int* in_sizes, int n_in,
                              void* d_out, int out_size)
{
    const float* x  = (const float*)d_in[0];
    const float* Wq = (const float*)d_in[1];
    const float* Wk = (const float*)d_in[2];
    const float* Wv = (const float*)d_in[3];
    float* out = (float*)d_out;

    // Dynamic smem for attn_kernel: (64*68*2 + 64*260) floats = 101376 bytes
    static const int kAttnSmem = (64 * QS_STRIDE * 2 + 64 * SS_STRIDE) * (int)sizeof(float);
    cudaFuncSetAttribute(attn_kernel, cudaFuncAttributeMaxDynamicSharedMemorySize, kAttnSmem);

    dim3 grid1((Bb * Tt) / 64, 3);
    qkv_kernel<<<grid1, 256>>>(x, Wq, Wk, Wv);

    dim3 grid2(Tt / 64, Bb);
    attn_kernel<<<grid2, 256, kAttnSmem>>>(out);
}

// round 3
// speedup vs baseline: 2.5604x; 2.5604x over previous
#include <cuda_runtime.h>
#include <stdint.h>
#include <math.h>

#define Bb 256
#define Tt 256
#define Cc 384
#define Hh 64

// Scratch for Q, K, V projections ([B*T, H] each, fp32)
__device__ float g_q[Bb * Tt * Hh];
__device__ float g_k[Bb * Tt * Hh];
__device__ float g_v[Bb * Tt * Hh];

__device__ __forceinline__ uint32_t f2tf(float f) {
    uint32_t u;
    asm("cvt.rna.tf32.f32 %0, %1;" : "=r"(u) : "f"(f));
    return u;
}

__device__ __forceinline__ void mma8(float c[4], const uint32_t a[4], const uint32_t b[2]) {
    asm volatile(
        "mma.sync.aligned.m16n8k8.row.col.f32.tf32.tf32.f32 "
        "{%0,%1,%2,%3},{%4,%5,%6,%7},{%8,%9},{%0,%1,%2,%3};\n"
        : "+f"(c[0]), "+f"(c[1]), "+f"(c[2]), "+f"(c[3])
        : "r"(a[0]), "r"(a[1]), "r"(a[2]), "r"(a[3]), "r"(b[0]), "r"(b[1]));
}

// ---------------------------------------------------------------------------
// Kernel 1: fused QKV projection (TF32 tensor cores).
//   out[128? no: 64 rows x 192 cols] per block. N=192 = [Wq | Wk | Wv].
//   grid = 1024, block = 256 (8 warps: 2 m-warps x 4 n-warps).
//   Warp tile: 32 rows (2 x m16) x 48 cols (6 x n8). K chunk = 32.
// ---------------------------------------------------------------------------
__global__ __launch_bounds__(256) void qkv_mma(
    const float* __restrict__ x,
    const float* __restrict__ Wq,
    const float* __restrict__ Wk,
    const float* __restrict__ Wv)
{
    __shared__ uint32_t Xs[64][36];    // stride 36 -> bank (4r+k)%32, conflict-free
    __shared__ uint32_t Ws[32][200];   // 192 cols + pad; stride 200 -> (8k+n)%32, conflict-free

    const int tid  = threadIdx.x;
    const int lane = tid & 31;
    const int wid  = tid >> 5;
    const int gid  = lane >> 2;
    const int tig  = lane & 3;
    const int wm   = wid & 1;          // 0..1 -> row offset wm*32
    const int wn   = wid >> 1;         // 0..3 -> col offset wn*48
    const int row0 = blockIdx.x * 64;

    float acc[2][6][4] = {};

    for (int kk = 0; kk < Cc; kk += 32) {
        // Xs: 64x32 = 512 float4, 2 per thread
        #pragma unroll
        for (int t = 0; t < 2; t++) {
            int idx = tid + t * 256;
            int r = idx >> 3, c = (idx & 7) * 4;
            float4 v = *(const float4*)&x[(size_t)(row0 + r) * Cc + kk + c];
            Xs[r][c + 0] = f2tf(v.x); Xs[r][c + 1] = f2tf(v.y);
            Xs[r][c + 2] = f2tf(v.z); Xs[r][c + 3] = f2tf(v.w);
        }
        // Ws: 32x192 = 1536 float4, 6 per thread
        #pragma unroll
        for (int t = 0; t < 6; t++) {
            int idx = tid + t * 256;
            int r = idx / 48, c = (idx % 48) * 4;
            const float* W = (c < 64) ? Wq : (c < 128) ? Wk : Wv;
            float4 v = *(const float4*)&W[(size_t)(kk + r) * Hh + (c & 63)];
            Ws[r][c + 0] = f2tf(v.x); Ws[r][c + 1] = f2tf(v.y);
            Ws[r][c + 2] = f2tf(v.z); Ws[r][c + 3] = f2tf(v.w);
        }
        __syncthreads();

        #pragma unroll
        for (int k0 = 0; k0 < 32; k0 += 8) {
            uint32_t a[2][4], bf[6][2];
            #pragma unroll
            for (int mt = 0; mt < 2; mt++) {
                int r = wm * 32 + mt * 16;
                a[mt][0] = Xs[r + gid][k0 + tig];
                a[mt][1] = Xs[r + gid + 8][k0 + tig];
                a[mt][2] = Xs[r + gid][k0 + tig + 4];
                a[mt][3] = Xs[r + gid + 8][k0 + tig + 4];
            }
            #pragma unroll
            for (int nt = 0; nt < 6; nt++) {
                int n = wn * 48 + nt * 8 + gid;
                bf[nt][0] = Ws[k0 + tig][n];
                bf[nt][1] = Ws[k0 + tig + 4][n];
            }
            #pragma unroll
            for (int mt = 0; mt < 2; mt++)
                #pragma unroll
                for (int nt = 0; nt < 6; nt++)
                    mma8(acc[mt][nt], a[mt], bf[nt]);
        }
        __syncthreads();
    }

    // Store: select output matrix by global column
    #pragma unroll
    for (int mt = 0; mt < 2; mt++) {
        #pragma unroll
        for (int nt = 0; nt < 6; nt++) {
            int n = wn * 48 + nt * 8 + tig * 2;
            float* out = (n < 64) ? g_q : (n < 128) ? g_k : g_v;
            int nc = n & 63;
            int r = row0 + wm * 32 + mt * 16 + gid;
            *(float2*)&out[(size_t)r * Hh + nc] = make_float2(acc[mt][nt][0], acc[mt][nt][1]);
            *(float2*)&out[(size_t)(r + 8) * Hh + nc] = make_float2(acc[mt][nt][2], acc[mt][nt][3]);
        }
    }
}

// ---------------------------------------------------------------------------
// Kernel 2: causal attention, TF32 mma for QK^T and PV.
//   grid = (4, 256): blockIdx.x = 64-row query tile, blockIdx.y = batch.
//   8 warps: 4 m-warps (16 rows) x 2 n-warps (32 cols).
// Dynamic smem (uint32 words):
//   Qs : 64*68  (tf32, Q*scale)
//   KV : 64*72  (K tile stride 68 / V tile stride 72)
//   Ss : 64*260 (fp32 scores -> tf32 probs in place)
// ---------------------------------------------------------------------------
#define SSTR 260

__global__ __launch_bounds__(256) void attn_mma(float* __restrict__ out)
{
    extern __shared__ uint32_t sm[];
    uint32_t (*Qs)[68] = (uint32_t(*)[68])sm;
    uint32_t* KV = sm + 64 * 68;
    float*    Ss = (float*)(KV + 64 * 72);
    uint32_t* Su = (uint32_t*)Ss;

    const int tid  = threadIdx.x;
    const int lane = tid & 31;
    const int wid  = tid >> 5;
    const int gid  = lane >> 2;
    const int tig  = lane & 3;
    const int wm   = wid & 3;     // 0..3 -> rows wm*16
    const int wn   = wid >> 2;    // 0..1 -> cols wn*32
    const int qt   = blockIdx.x;
    const int b    = blockIdx.y;
    const int q0   = qt * 64;
    const float scale = rsqrtf((float)Cc);   // C**-0.5 per reference

    // Load Q tile, pre-scaled, tf32
    #pragma unroll
    for (int t = 0; t < 4; t++) {
        int idx = tid + t * 256;
        int r = idx >> 4, c = (idx & 15) * 4;
        float4 v = *(const float4*)&g_q[(size_t)(b * Tt + q0 + r) * Hh + c];
        Qs[r][c + 0] = f2tf(v.x * scale); Qs[r][c + 1] = f2tf(v.y * scale);
        Qs[r][c + 2] = f2tf(v.z * scale); Qs[r][c + 3] = f2tf(v.w * scale);
    }

    // ---- S = (Q*scale) K^T, masked, fp32 to Ss ----
    for (int jt = 0; jt <= qt; jt++) {
        __syncthreads();  // protect KV reuse (and Q on first iter)
        #pragma unroll
        for (int t = 0; t < 4; t++) {
            int idx = tid + t * 256;
            int r = idx >> 4, c = (idx & 15) * 4;
            float4 v = *(const float4*)&g_k[(size_t)(b * Tt + jt * 64 + r) * Hh + c];
            KV[r * 68 + c + 0] = f2tf(v.x); KV[r * 68 + c + 1] = f2tf(v.y);
            KV[r * 68 + c + 2] = f2tf(v.z); KV[r * 68 + c + 3] = f2tf(v.w);
        }
        __syncthreads();

        float c4[4][4] = {};
        #pragma unroll
        for (int k0 = 0; k0 < 64; k0 += 8) {
            uint32_t a[4], bf[4][2];
            int r = wm * 16;
            a[0] = Qs[r + gid][k0 + tig];
            a[1] = Qs[r + gid + 8][k0 + tig];
            a[2] = Qs[r + gid][k0 + tig + 4];
            a[3] = Qs[r + gid + 8][k0 + tig + 4];
            #pragma unroll
            for (int nt = 0; nt < 4; nt++) {
                int n = wn * 32 + nt * 8 + gid;        // key index in tile
                bf[nt][0] = KV[n * 68 + k0 + tig];     // K[key][h] == col-major B
                bf[nt][1] = KV[n * 68 + k0 + tig + 4];
            }
            #pragma unroll
            for (int nt = 0; nt < 4; nt++) mma8(c4[nt], a, bf[nt]);
        }

        const bool needmask = (jt == qt);
        #pragma unroll
        for (int nt = 0; nt < 4; nt++) {
            int colb = wn * 32 + nt * 8 + tig * 2;      // within-tile key col
            int kg   = jt * 64 + colb;                  // global key
            int row  = wm * 16 + gid;
            int qg0  = q0 + row, qg1 = q0 + row + 8;
            float s0 = (!needmask || kg     <= qg0) ? c4[nt][0] : -1e30f;
            float s1 = (!needmask || kg + 1 <= qg0) ? c4[nt][1] : -1e30f;
            float s2 = (!needmask || kg     <= qg1) ? c4[nt][2] : -1e30f;
            float s3 = (!needmask || kg + 1 <= qg1) ? c4[nt][3] : -1e30f;
            Ss[row * SSTR + jt * 64 + colb]           = s0;
            Ss[row * SSTR + jt * 64 + colb + 1]       = s1;
            Ss[(row + 8) * SSTR + jt * 64 + colb]     = s2;
            Ss[(row + 8) * SSTR + jt * 64 + colb + 1] = s3;
        }
    }
    __syncthreads();

    // ---- softmax (4 lanes per row), write back tf32 probabilities ----
    {
        const int ncol = (qt + 1) * 64;
        const int row  = tid >> 2;
        const int sub  = tid & 3;
        float* rp = &Ss[row * SSTR];

        float m = -1e30f;
        for (int c = sub; c < ncol; c += 4) m = fmaxf(m, rp[c]);
        m = fmaxf(m, __shfl_xor_sync(0xffffffffu, m, 1));
        m = fmaxf(m, __shfl_xor_sync(0xffffffffu, m, 2));

        float s = 0.f;
        for (int c = sub; c < ncol; c += 4) {
            float e = __expf(rp[c] - m);
            rp[c] = e;
            s += e;
        }
        s += __shfl_xor_sync(0xffffffffu, s, 1);
        s += __shfl_xor_sync(0xffffffffu, s, 2);
        float inv = 1.f / s;

        uint32_t* ru = (uint32_t*)rp;
        for (int c = sub; c < ncol; c += 4) ru[c] = f2tf(rp[c] * inv);
    }

    // ---- O = P V ----
    float o[4][4] = {};
    for (int jt = 0; jt <= qt; jt++) {
        __syncthreads();  // softmax writes / previous KV reads done
        #pragma unroll
        for (int t = 0; t < 4; t++) {
            int idx = tid + t * 256;
            int r = idx >> 4, c = (idx & 15) * 4;
            float4 v = *(const float4*)&g_v[(size_t)(b * Tt + jt * 64 + r) * Hh + c];
            KV[r * 72 + c + 0] = f2tf(v.x); KV[r * 72 + c + 1] = f2tf(v.y);
            KV[r * 72 + c + 2] = f2tf(v.z); KV[r * 72 + c + 3] = f2tf(v.w);
        }
        __syncthreads();

        #pragma unroll
        for (int k0 = 0; k0 < 64; k0 += 8) {
            uint32_t a[4], bf[4][2];
            int r = wm * 16;
            int kc = jt * 64 + k0;
            a[0] = Su[(r + gid) * SSTR + kc + tig];
            a[1] = Su[(r + gid + 8) * SSTR + kc + tig];
            a[2] = Su[(r + gid) * SSTR + kc + tig + 4];
            a[3] = Su[(r + gid + 8) * SSTR + kc + tig + 4];
            #pragma unroll
            for (int nt = 0; nt < 4; nt++) {
                int n = wn * 32 + nt * 8 + gid;          // h column
                bf[nt][0] = KV[(k0 + tig) * 72 + n];     // V[key][h], stride 72
                bf[nt][1] = KV[(k0 + tig + 4) * 72 + n];
            }
            #pragma unroll
            for (int nt = 0; nt < 4; nt++) mma8(o[nt], a, bf[nt]);
        }
    }

    // Store output [B, T, H] fp32
    #pragma unroll
    for (int nt = 0; nt < 4; nt++) {
        int col = wn * 32 + nt * 8 + tig * 2;
        int row = q0 + wm * 16 + gid;
        *(float2*)&out[(size_t)(b * Tt + row) * Hh + col] = make_float2(o[nt][0], o[nt][1]);
        *(float2*)&out[(size_t)(b * Tt + row + 8) * Hh + col] = make_float2(o[nt][2], o[nt][3]);
    }
}

// ---------------------------------------------------------------------------
extern "C" void kernel_launch(void* const* d_in, const int* in_sizes, int n_in,
                              void* d_out, int out_size)
{
    const float* x  = (const float*)d_in[0];
    const float* Wq = (const float*)d_in[1];
    const float* Wk = (const float*)d_in[2];
    const float* Wv = (const float*)d_in[3];
    float* out = (float*)d_out;

    static const int kAttnSmem = (64 * 68 + 64 * 72 + 64 * SSTR) * (int)sizeof(uint32_t);
    cudaFuncSetAttribute(attn_mma, cudaFuncAttributeMaxDynamicSharedMemorySize, kAttnSmem);

    qkv_mma<<<(Bb * Tt) / 64, 256>>>(x, Wq, Wk, Wv);

    dim3 grid2(Tt / 64, Bb);
    attn_mma<<<grid2, 256, kAttnSmem>>>(out);
}

// round 4
// speedup vs baseline: 2.7080x; 1.0577x over previous
#include <cuda_runtime.h>
#include <stdint.h>
#include <math.h>

#define Bb 256
#define Tt 256
#define Cc 384
#define Hh 64
#define Nqkv 192
#define SSTR 260

// Scratch: projections (tf32-rounded fp32; Q pre-scaled) + pre-converted weights
__device__ float g_q[Bb * Tt * Hh];
__device__ float g_k[Bb * Tt * Hh];
__device__ float g_v[Bb * Tt * Hh];
__device__ float g_wt[Cc * Nqkv];

__device__ __forceinline__ uint32_t f2tf(float f) {
    uint32_t u;
    asm("cvt.rna.tf32.f32 %0, %1;" : "=r"(u) : "f"(f));
    return u;
}
__device__ __forceinline__ uint32_t smaddr(const void* p) {
    return (uint32_t)__cvta_generic_to_shared(p);
}
__device__ __forceinline__ void cpa16(uint32_t d, const void* s) {
    asm volatile("cp.async.cg.shared.global [%0], [%1], 16;\n" :: "r"(d), "l"(s));
}
__device__ __forceinline__ void cp_commit() { asm volatile("cp.async.commit_group;\n"); }
__device__ __forceinline__ void cp_wait0()  { asm volatile("cp.async.wait_group 0;\n" ::: "memory"); }

__device__ __forceinline__ void mma8(float c[4], const uint32_t a[4], const uint32_t b[2]) {
    asm volatile(
        "mma.sync.aligned.m16n8k8.row.col.f32.tf32.tf32.f32 "
        "{%0,%1,%2,%3},{%4,%5,%6,%7},{%8,%9},{%0,%1,%2,%3};\n"
        : "+f"(c[0]), "+f"(c[1]), "+f"(c[2]), "+f"(c[3])
        : "r"(a[0]), "r"(a[1]), "r"(a[2]), "r"(a[3]), "r"(b[0]), "r"(b[1]));
}

// ---------------------------------------------------------------------------
// Kernel 0: round [Wq|Wk|Wv] to tf32 once. g_wt layout [k][192].
// ---------------------------------------------------------------------------
__global__ __launch_bounds__(512) void prep_w(
    const float* __restrict__ Wq, const float* __restrict__ Wk, const float* __restrict__ Wv)
{
    int idx = blockIdx.x * 512 + threadIdx.x;     // 144 blocks -> 73728 elements
    int k = idx / Nqkv, n = idx % Nqkv;
    const float* W = (n < 64) ? Wq : (n < 128) ? Wk : Wv;
    g_wt[idx] = __uint_as_float(f2tf(W[k * Hh + (n & 63)]));
}

// ---------------------------------------------------------------------------
// Kernel 1: fused QKV projection, 128x192 block tile, cp.async double-buffered.
//   512 threads = 16 warps: 4 m-warps (32 rows) x 4 n-warps (48 cols).
// Dynamic smem: Xs[2][128][36] fp32 raw, Ws[2][32][200] tf32.
// ---------------------------------------------------------------------------
__global__ __launch_bounds__(512) void qkv_mma(const float* __restrict__ x)
{
    extern __shared__ uint32_t sm[];
    float* Xs = (float*)sm;                  // 2*128*36
    float* Ws = (float*)(sm + 2 * 128 * 36); // 2*32*200

    const int tid  = threadIdx.x;
    const int lane = tid & 31;
    const int wid  = tid >> 5;
    const int gid  = lane >> 2;
    const int tig  = lane & 3;
    const int wm   = wid & 3;
    const int wn   = wid >> 2;
    const int row0 = blockIdx.x * 128;

    auto issue = [&](int chunk) {
        int buf = chunk & 1;
        float* Xb = Xs + buf * 128 * 36;
        float* Wb = Ws + buf * 32 * 200;
        int kk = chunk * 32;
        #pragma unroll
        for (int i = 0; i < 2; i++) {
            int idx = tid + i * 512;
            int r = idx >> 3, c = (idx & 7) * 4;
            cpa16(smaddr(&Xb[r * 36 + c]), &x[(size_t)(row0 + r) * Cc + kk + c]);
        }
        #pragma unroll
        for (int i = 0; i < 3; i++) {
            int idx = tid + i * 512;
            int r = idx / 48, c = (idx % 48) * 4;
            cpa16(smaddr(&Wb[r * 200 + c]), &g_wt[(size_t)(kk + r) * Nqkv + c]);
        }
        cp_commit();
    };

    float acc[2][6][4] = {};
    issue(0);

    for (int ch = 0; ch < 12; ch++) {
        cp_wait0();
        __syncthreads();
        if (ch < 11) issue(ch + 1);

        const float* Xb = Xs + (ch & 1) * 128 * 36;
        const float* Wb = Ws + (ch & 1) * 32 * 200;

        #pragma unroll
        for (int k0 = 0; k0 < 32; k0 += 8) {
            uint32_t a[2][4], bf[6][2];
            #pragma unroll
            for (int mt = 0; mt < 2; mt++) {
                int r = wm * 32 + mt * 16;
                a[mt][0] = f2tf(Xb[(r + gid) * 36 + k0 + tig]);
                a[mt][1] = f2tf(Xb[(r + gid + 8) * 36 + k0 + tig]);
                a[mt][2] = f2tf(Xb[(r + gid) * 36 + k0 + tig + 4]);
                a[mt][3] = f2tf(Xb[(r + gid + 8) * 36 + k0 + tig + 4]);
            }
            #pragma unroll
            for (int nt = 0; nt < 6; nt++) {
                int n = wn * 48 + nt * 8 + gid;
                bf[nt][0] = __float_as_uint(Wb[(k0 + tig) * 200 + n]);
                bf[nt][1] = __float_as_uint(Wb[(k0 + tig + 4) * 200 + n]);
            }
            #pragma unroll
            for (int mt = 0; mt < 2; mt++)
                #pragma unroll
                for (int nt = 0; nt < 6; nt++)
                    mma8(acc[mt][nt], a[mt], bf[nt]);
        }
    }

    // Store tf32-rounded; Q pre-scaled by C^-0.5
    const float scale = rsqrtf((float)Cc);
    #pragma unroll
    for (int mt = 0; mt < 2; mt++) {
        #pragma unroll
        for (int nt = 0; nt < 6; nt++) {
            int n = wn * 48 + nt * 8 + tig * 2;
            float* outp = (n < 64) ? g_q : (n < 128) ? g_k : g_v;
            float sc = (n < 64) ? scale : 1.0f;
            int nc = n & 63;
            int r = row0 + wm * 32 + mt * 16 + gid;
            float2 v0 = make_float2(__uint_as_float(f2tf(acc[mt][nt][0] * sc)),
                                    __uint_as_float(f2tf(acc[mt][nt][1] * sc)));
            float2 v1 = make_float2(__uint_as_float(f2tf(acc[mt][nt][2] * sc)),
                                    __uint_as_float(f2tf(acc[mt][nt][3] * sc)));
            *(float2*)&outp[(size_t)r * Hh + nc] = v0;
            *(float2*)&outp[(size_t)(r + 8) * Hh + nc] = v1;
        }
    }
}

// ---------------------------------------------------------------------------
// Kernel 2: causal attention, 128-row query tiles, cp.async double-buffered K/V.
//   grid = (2, 256). 512 threads = 16 warps: 8 m-warps (16 rows) x 2 n-warps (32 cols).
// Dynamic smem (words): Qs 128*68 | KV 2*64*72 | Ss 128*260
// All inputs already tf32-rounded (Q pre-scaled) -> zero cvt on loads.
// ---------------------------------------------------------------------------
__global__ __launch_bounds__(512) void attn_mma(float* __restrict__ out)
{
    extern __shared__ uint32_t sm[];
    uint32_t* Qs = sm;                        // 128*68
    uint32_t* KV = sm + 128 * 68;             // 2 * 64*72
    float*    Ss = (float*)(KV + 2 * 64 * 72);
    uint32_t* Su = (uint32_t*)Ss;

    const int tid  = threadIdx.x;
    const int lane = tid & 31;
    const int wid  = tid >> 5;
    const int gid  = lane >> 2;
    const int tig  = lane & 3;
    const int wm   = wid & 7;      // rows wm*16
    const int wn   = wid >> 3;     // cols wn*32
    const int qt   = blockIdx.x;   // 0..1
    const int b    = blockIdx.y;
    const int q0   = qt * 128;
    const int nT   = 2 * qt + 2;   // key tiles present
    const int lastT = nT - 1;

    // Prologue: Q tile + K tile 0 in one group
    #pragma unroll
    for (int i = 0; i < 4; i++) {
        int idx = tid + i * 512;
        int r = idx >> 4, c = (idx & 15) * 4;
        cpa16(smaddr(&Qs[r * 68 + c]), &g_q[(size_t)(b * Tt + q0 + r) * Hh + c]);
    }
    #pragma unroll
    for (int i = 0; i < 2; i++) {
        int idx = tid + i * 512;
        int r = idx >> 4, c = (idx & 15) * 4;
        cpa16(smaddr(&KV[r * 72 + c]), &g_k[(size_t)(b * Tt + r) * Hh + c]);
    }
    cp_commit();

    // ---- S phase ----
    for (int jt = 0; jt <= lastT; jt++) {
        cp_wait0();
        __syncthreads();
        if (jt < lastT) {
            uint32_t* Kb = KV + ((jt + 1) & 1) * 64 * 72;
            #pragma unroll
            for (int i = 0; i < 2; i++) {
                int idx = tid + i * 512;
                int r = idx >> 4, c = (idx & 15) * 4;
                cpa16(smaddr(&Kb[r * 72 + c]),
                      &g_k[(size_t)(b * Tt + (jt + 1) * 64 + r) * Hh + c]);
            }
            cp_commit();
        }

        const uint32_t* Kb = KV + (jt & 1) * 64 * 72;
        float c4[4][4] = {};
        #pragma unroll
        for (int k0 = 0; k0 < 64; k0 += 8) {
            uint32_t a[4], bf[4][2];
            int r = wm * 16;
            a[0] = Qs[(r + gid) * 68 + k0 + tig];
            a[1] = Qs[(r + gid + 8) * 68 + k0 + tig];
            a[2] = Qs[(r + gid) * 68 + k0 + tig + 4];
            a[3] = Qs[(r + gid + 8) * 68 + k0 + tig + 4];
            #pragma unroll
            for (int nt = 0; nt < 4; nt++) {
                int n = wn * 32 + nt * 8 + gid;
                bf[nt][0] = Kb[n * 72 + k0 + tig];
                bf[nt][1] = Kb[n * 72 + k0 + tig + 4];
            }
            #pragma unroll
            for (int nt = 0; nt < 4; nt++) mma8(c4[nt], a, bf[nt]);
        }

        const bool mayMask = (jt * 64 + 63 > q0);
        #pragma unroll
        for (int nt = 0; nt < 4; nt++) {
            int colb = wn * 32 + nt * 8 + tig * 2;
            int kg   = jt * 64 + colb;
            int row  = wm * 16 + gid;
            int qg0  = q0 + row, qg1 = q0 + row + 8;
            float s0 = (!mayMask || kg     <= qg0) ? c4[nt][0] : -1e30f;
            float s1 = (!mayMask || kg + 1 <= qg0) ? c4[nt][1] : -1e30f;
            float s2 = (!mayMask || kg     <= qg1) ? c4[nt][2] : -1e30f;
            float s3 = (!mayMask || kg + 1 <= qg1) ? c4[nt][3] : -1e30f;
            *(float2*)&Ss[row * SSTR + jt * 64 + colb]       = make_float2(s0, s1);
            *(float2*)&Ss[(row + 8) * SSTR + jt * 64 + colb] = make_float2(s2, s3);
        }
    }
    __syncthreads();

    // Prefetch V tile 0 (overlaps with softmax)
    #pragma unroll
    for (int i = 0; i < 2; i++) {
        int idx = tid + i * 512;
        int r = idx >> 4, c = (idx & 15) * 4;
        cpa16(smaddr(&KV[r * 72 + c]), &g_v[(size_t)(b * Tt + r) * Hh + c]);
    }
    cp_commit();

    // ---- softmax (4 lanes per row); write back tf32 probabilities ----
    {
        const int ncol = nT * 64;
        const int row  = tid >> 2;
        const int sub  = tid & 3;
        float* rp = &Ss[row * SSTR];

        float m = -1e30f;
        for (int c = sub; c < ncol; c += 4) m = fmaxf(m, rp[c]);
        m = fmaxf(m, __shfl_xor_sync(0xffffffffu, m, 1));
        m = fmaxf(m, __shfl_xor_sync(0xffffffffu, m, 2));

        float s = 0.f;
        for (int c = sub; c < ncol; c += 4) {
            float e = __expf(rp[c] - m);
            rp[c] = e;
            s += e;
        }
        s += __shfl_xor_sync(0xffffffffu, s, 1);
        s += __shfl_xor_sync(0xffffffffu, s, 2);
        float inv = 1.f / s;

        uint32_t* ru = (uint32_t*)rp;
        for (int c = sub; c < ncol; c += 4) ru[c] = f2tf(rp[c] * inv);
    }

    // ---- PV phase ----
    float o[4][4] = {};
    for (int jt = 0; jt <= lastT; jt++) {
        cp_wait0();
        __syncthreads();
        if (jt < lastT) {
            uint32_t* Vb = KV + ((jt + 1) & 1) * 64 * 72;
            #pragma unroll
            for (int i = 0; i < 2; i++) {
                int idx = tid + i * 512;
                int r = idx >> 4, c = (idx & 15) * 4;
                cpa16(smaddr(&Vb[r * 72 + c]),
                      &g_v[(size_t)(b * Tt + (jt + 1) * 64 + r) * Hh + c]);
            }
            cp_commit();
        }

        const uint32_t* Vb = KV + (jt & 1) * 64 * 72;
        #pragma unroll
        for (int k0 = 0; k0 < 64; k0 += 8) {
            uint32_t a[4], bf[4][2];
            int r = wm * 16, kc = jt * 64 + k0;
            a[0] = Su[(r + gid) * SSTR + kc + tig];
            a[1] = Su[(r + gid + 8) * SSTR + kc + tig];
            a[2] = Su[(r + gid) * SSTR + kc + tig + 4];
            a[3] = Su[(r + gid + 8) * SSTR + kc + tig + 4];
            #pragma unroll
            for (int nt = 0; nt < 4; nt++) {
                int n = wn * 32 + nt * 8 + gid;
                bf[nt][0] = Vb[(k0 + tig) * 72 + n];
                bf[nt][1] = Vb[(k0 + tig + 4) * 72 + n];
            }
            #pragma unroll
            for (int nt = 0; nt < 4; nt++) mma8(o[nt], a, bf[nt]);
        }
    }

    // Store output [B, T, H] fp32
    #pragma unroll
    for (int nt = 0; nt < 4; nt++) {
        int col = wn * 32 + nt * 8 + tig * 2;
        int row = q0 + wm * 16 + gid;
        *(float2*)&out[(size_t)(b * Tt + row) * Hh + col] = make_float2(o[nt][0], o[nt][1]);
        *(float2*)&out[(size_t)(b * Tt + row + 8) * Hh + col] = make_float2(o[nt][2], o[nt][3]);
    }
}

// ---------------------------------------------------------------------------
extern "C" void kernel_launch(void* const* d_in, const int* in_sizes, int n_in,
                              void* d_out, int out_size)
{
    const float* x  = (const float*)d_in[0];
    const float* Wq = (const float*)d_in[1];
    const float* Wk = (const float*)d_in[2];
    const float* Wv = (const float*)d_in[3];
    float* out = (float*)d_out;

    static const int kQkvSmem  = (2 * 128 * 36 + 2 * 32 * 200) * (int)sizeof(uint32_t);  // 88064
    static const int kAttnSmem = (128 * 68 + 2 * 64 * 72 + 128 * SSTR) * (int)sizeof(uint32_t); // 204800
    cudaFuncSetAttribute(qkv_mma, cudaFuncAttributeMaxDynamicSharedMemorySize, kQkvSmem);
    cudaFuncSetAttribute(attn_mma, cudaFuncAttributeMaxDynamicSharedMemorySize, kAttnSmem);

    prep_w<<<144, 512>>>(Wq, Wk, Wv);
    qkv_mma<<<(Bb * Tt) / 128, 512, kQkvSmem>>>(x);

    dim3 grid2(Tt / 128, Bb);
    attn_mma<<<grid2, 512, kAttnSmem>>>(out);
}

// round 5
// speedup vs baseline: 3.1827x; 1.1753x over previous
#include <cuda_runtime.h>
#include <stdint.h>
#include <math.h>

#define Bb 256
#define Tt 256
#define Cc 384
#define Hh 64
#define Nqkv 192

// Scratch: projections (tf32-rounded fp32; Q pre-scaled) + pre-converted weights
__device__ float g_q[Bb * Tt * Hh];
__device__ float g_k[Bb * Tt * Hh];
__device__ float g_v[Bb * Tt * Hh];
__device__ float g_wt[Cc * Nqkv];

__device__ __forceinline__ uint32_t f2tf(float f) {
    uint32_t u;
    asm("cvt.rna.tf32.f32 %0, %1;" : "=r"(u) : "f"(f));
    return u;
}
__device__ __forceinline__ uint32_t smaddr(const void* p) {
    return (uint32_t)__cvta_generic_to_shared(p);
}
__device__ __forceinline__ void cpa16(uint32_t d, const void* s) {
    asm volatile("cp.async.cg.shared.global [%0], [%1], 16;\n" :: "r"(d), "l"(s));
}
__device__ __forceinline__ void cp_commit() { asm volatile("cp.async.commit_group;\n"); }
__device__ __forceinline__ void cp_wait0()  { asm volatile("cp.async.wait_group 0;\n" ::: "memory"); }

__device__ __forceinline__ void mma8(float c[4], const uint32_t a[4], const uint32_t b[2]) {
    asm volatile(
        "mma.sync.aligned.m16n8k8.row.col.f32.tf32.tf32.f32 "
        "{%0,%1,%2,%3},{%4,%5,%6,%7},{%8,%9},{%0,%1,%2,%3};\n"
        : "+f"(c[0]), "+f"(c[1]), "+f"(c[2]), "+f"(c[3])
        : "r"(a[0]), "r"(a[1]), "r"(a[2]), "r"(a[3]), "r"(b[0]), "r"(b[1]));
}

// ---------------------------------------------------------------------------
// Kernel 0: round [Wq|Wk|Wv] to tf32 once. g_wt layout [k][192].
// ---------------------------------------------------------------------------
__global__ __launch_bounds__(512) void prep_w(
    const float* __restrict__ Wq, const float* __restrict__ Wk, const float* __restrict__ Wv)
{
    int idx = blockIdx.x * 512 + threadIdx.x;
    int k = idx / Nqkv, n = idx % Nqkv;
    const float* W = (n < 64) ? Wq : (n < 128) ? Wk : Wv;
    g_wt[idx] = __uint_as_float(f2tf(W[k * Hh + (n & 63)]));
}

// ---------------------------------------------------------------------------
// Kernel 1: fused QKV projection, 128x192 block tile, cp.async double-buffered.
// (unchanged from R4 — known good; next round's target)
// ---------------------------------------------------------------------------
__global__ __launch_bounds__(512) void qkv_mma(const float* __restrict__ x)
{
    extern __shared__ uint32_t sm[];
    float* Xs = (float*)sm;                  // 2*128*36
    float* Ws = (float*)(sm + 2 * 128 * 36); // 2*32*200

    const int tid  = threadIdx.x;
    const int lane = tid & 31;
    const int wid  = tid >> 5;
    const int gid  = lane >> 2;
    const int tig  = lane & 3;
    const int wm   = wid & 3;
    const int wn   = wid >> 2;
    const int row0 = blockIdx.x * 128;

    auto issue = [&](int chunk) {
        int buf = chunk & 1;
        float* Xb = Xs + buf * 128 * 36;
        float* Wb = Ws + buf * 32 * 200;
        int kk = chunk * 32;
        #pragma unroll
        for (int i = 0; i < 2; i++) {
            int idx = tid + i * 512;
            int r = idx >> 3, c = (idx & 7) * 4;
            cpa16(smaddr(&Xb[r * 36 + c]), &x[(size_t)(row0 + r) * Cc + kk + c]);
        }
        #pragma unroll
        for (int i = 0; i < 3; i++) {
            int idx = tid + i * 512;
            int r = idx / 48, c = (idx % 48) * 4;
            cpa16(smaddr(&Wb[r * 200 + c]), &g_wt[(size_t)(kk + r) * Nqkv + c]);
        }
        cp_commit();
    };

    float acc[2][6][4] = {};
    issue(0);

    for (int ch = 0; ch < 12; ch++) {
        cp_wait0();
        __syncthreads();
        if (ch < 11) issue(ch + 1);

        const float* Xb = Xs + (ch & 1) * 128 * 36;
        const float* Wb = Ws + (ch & 1) * 32 * 200;

        #pragma unroll
        for (int k0 = 0; k0 < 32; k0 += 8) {
            uint32_t a[2][4], bf[6][2];
            #pragma unroll
            for (int mt = 0; mt < 2; mt++) {
                int r = wm * 32 + mt * 16;
                a[mt][0] = f2tf(Xb[(r + gid) * 36 + k0 + tig]);
                a[mt][1] = f2tf(Xb[(r + gid + 8) * 36 + k0 + tig]);
                a[mt][2] = f2tf(Xb[(r + gid) * 36 + k0 + tig + 4]);
                a[mt][3] = f2tf(Xb[(r + gid + 8) * 36 + k0 + tig + 4]);
            }
            #pragma unroll
            for (int nt = 0; nt < 6; nt++) {
                int n = wn * 48 + nt * 8 + gid;
                bf[nt][0] = __float_as_uint(Wb[(k0 + tig) * 200 + n]);
                bf[nt][1] = __float_as_uint(Wb[(k0 + tig + 4) * 200 + n]);
            }
            #pragma unroll
            for (int mt = 0; mt < 2; mt++)
                #pragma unroll
                for (int nt = 0; nt < 6; nt++)
                    mma8(acc[mt][nt], a[mt], bf[nt]);
        }
    }

    const float scale = rsqrtf((float)Cc);
    #pragma unroll
    for (int mt = 0; mt < 2; mt++) {
        #pragma unroll
        for (int nt = 0; nt < 6; nt++) {
            int n = wn * 48 + nt * 8 + tig * 2;
            float* outp = (n < 64) ? g_q : (n < 128) ? g_k : g_v;
            float sc = (n < 64) ? scale : 1.0f;
            int nc = n & 63;
            int r = row0 + wm * 32 + mt * 16 + gid;
            float2 v0 = make_float2(__uint_as_float(f2tf(acc[mt][nt][0] * sc)),
                                    __uint_as_float(f2tf(acc[mt][nt][1] * sc)));
            float2 v1 = make_float2(__uint_as_float(f2tf(acc[mt][nt][2] * sc)),
                                    __uint_as_float(f2tf(acc[mt][nt][3] * sc)));
            *(float2*)&outp[(size_t)r * Hh + nc] = v0;
            *(float2*)&outp[(size_t)(r + 8) * Hh + nc] = v1;
        }
    }
}

// ---------------------------------------------------------------------------
// Kernel 2: flash-attention, single pass, online softmax.
//   grid (2,256), 256 threads = 8 warps. Block = 128 q-rows; warp = 16 rows.
//   Q in registers; per-warp P staging (no block sync); causal warp skipping.
// Smem (words): QP 128*68 | K 2*64*68 | V 2*64*72   = 106496 bytes
// ---------------------------------------------------------------------------
__global__ __launch_bounds__(256, 2) void attn_flash(float* __restrict__ out)
{
    extern __shared__ uint32_t sm[];
    uint32_t* QP = sm;                 // 128*68 (Q stage, then P staging)
    uint32_t* Kb = sm + 128 * 68;      // 2 * 64*68
    uint32_t* Vb = Kb + 2 * 64 * 68;   // 2 * 64*72

    const int tid  = threadIdx.x;
    const int lane = tid & 31;
    const int wid  = tid >> 5;          // warp = 16 q-rows
    const int gid  = lane >> 2;
    const int tig  = lane & 3;
    const int qt   = 1 - blockIdx.x;    // heavy blocks first
    const int b    = blockIdx.y;
    const int q0   = qt * 128;
    const int r0   = wid * 16;          // warp row base (block-local)
    const int lastT = 2 * qt + 1;
    const int dtile = (q0 + r0) >> 6;   // warp's diagonal key tile

    // ---- Prologue: stage Q + K0 + V0 ----
    #pragma unroll
    for (int i = 0; i < 8; i++) {
        int idx = tid + i * 256;
        int r = idx >> 4, c = (idx & 15) * 4;
        cpa16(smaddr(&QP[r * 68 + c]), &g_q[(size_t)(b * Tt + q0 + r) * Hh + c]);
    }
    #pragma unroll
    for (int i = 0; i < 4; i++) {
        int idx = tid + i * 256;
        int r = idx >> 4, c = (idx & 15) * 4;
        cpa16(smaddr(&Kb[r * 68 + c]), &g_k[(size_t)(b * Tt + r) * Hh + c]);
        cpa16(smaddr(&Vb[r * 72 + c]), &g_v[(size_t)(b * Tt + r) * Hh + c]);
    }
    cp_commit();
    cp_wait0();
    __syncthreads();

    // Q fragments -> registers (32 regs), warp reads only its own rows
    uint32_t Qa[8][4];
    #pragma unroll
    for (int k0 = 0; k0 < 8; k0++) {
        Qa[k0][0] = QP[(r0 + gid) * 68 + k0 * 8 + tig];
        Qa[k0][1] = QP[(r0 + gid + 8) * 68 + k0 * 8 + tig];
        Qa[k0][2] = QP[(r0 + gid) * 68 + k0 * 8 + tig + 4];
        Qa[k0][3] = QP[(r0 + gid + 8) * 68 + k0 * 8 + tig + 4];
    }
    __syncthreads();   // QP now reusable as P staging

    float o[8][4] = {};
    float m0 = -1e30f, m1 = -1e30f, l0 = 0.f, l1 = 0.f;

    for (int jt = 0; jt <= lastT; jt++) {
        // Prefetch next K/V tile into other buffer
        if (jt < lastT) {
            uint32_t* Kn = Kb + ((jt + 1) & 1) * 64 * 68;
            uint32_t* Vn = Vb + ((jt + 1) & 1) * 64 * 72;
            #pragma unroll
            for (int i = 0; i < 4; i++) {
                int idx = tid + i * 256;
                int r = idx >> 4, c = (idx & 15) * 4;
                cpa16(smaddr(&Kn[r * 68 + c]), &g_k[(size_t)(b * Tt + (jt + 1) * 64 + r) * Hh + c]);
                cpa16(smaddr(&Vn[r * 72 + c]), &g_v[(size_t)(b * Tt + (jt + 1) * 64 + r) * Hh + c]);
            }
            cp_commit();
        }

        if (jt <= dtile) {
            const uint32_t* K = Kb + (jt & 1) * 64 * 68;
            const uint32_t* V = Vb + (jt & 1) * 64 * 72;

            // ---- S = Q K^T for this warp's 16 rows x 64 keys ----
            float c4[8][4] = {};
            #pragma unroll
            for (int k0 = 0; k0 < 8; k0++) {
                uint32_t bf[8][2];
                #pragma unroll
                for (int nt = 0; nt < 8; nt++) {
                    int n = nt * 8 + gid;
                    bf[nt][0] = K[n * 68 + k0 * 8 + tig];
                    bf[nt][1] = K[n * 68 + k0 * 8 + tig + 4];
                }
                #pragma unroll
                for (int nt = 0; nt < 8; nt++) mma8(c4[nt], Qa[k0], bf[nt]);
            }

            // Causal mask (only on the diagonal tile)
            if (jt == dtile) {
                int qg0 = q0 + r0 + gid, qg1 = qg0 + 8;
                #pragma unroll
                for (int nt = 0; nt < 8; nt++) {
                    int kg = jt * 64 + nt * 8 + tig * 2;
                    if (kg     > qg0) c4[nt][0] = -1e30f;
                    if (kg + 1 > qg0) c4[nt][1] = -1e30f;
                    if (kg     > qg1) c4[nt][2] = -1e30f;
                    if (kg + 1 > qg1) c4[nt][3] = -1e30f;
                }
            }

            // ---- online softmax update ----
            float mx0 = -1e30f, mx1 = -1e30f;
            #pragma unroll
            for (int nt = 0; nt < 8; nt++) {
                mx0 = fmaxf(mx0, fmaxf(c4[nt][0], c4[nt][1]));
                mx1 = fmaxf(mx1, fmaxf(c4[nt][2], c4[nt][3]));
            }
            mx0 = fmaxf(mx0, __shfl_xor_sync(0xffffffffu, mx0, 1));
            mx0 = fmaxf(mx0, __shfl_xor_sync(0xffffffffu, mx0, 2));
            mx1 = fmaxf(mx1, __shfl_xor_sync(0xffffffffu, mx1, 1));
            mx1 = fmaxf(mx1, __shfl_xor_sync(0xffffffffu, mx1, 2));

            float m0n = fmaxf(m0, mx0), m1n = fmaxf(m1, mx1);
            float a0 = __expf(m0 - m0n), a1 = __expf(m1 - m1n);
            m0 = m0n; m1 = m1n;

            float s0 = 0.f, s1 = 0.f;
            #pragma unroll
            for (int nt = 0; nt < 8; nt++) {
                c4[nt][0] = __expf(c4[nt][0] - m0n);
                c4[nt][1] = __expf(c4[nt][1] - m0n);
                c4[nt][2] = __expf(c4[nt][2] - m1n);
                c4[nt][3] = __expf(c4[nt][3] - m1n);
                s0 += c4[nt][0] + c4[nt][1];
                s1 += c4[nt][2] + c4[nt][3];
            }
            s0 += __shfl_xor_sync(0xffffffffu, s0, 1);
            s0 += __shfl_xor_sync(0xffffffffu, s0, 2);
            s1 += __shfl_xor_sync(0xffffffffu, s1, 1);
            s1 += __shfl_xor_sync(0xffffffffu, s1, 2);
            l0 = l0 * a0 + s0;
            l1 = l1 * a1 + s1;

            #pragma unroll
            for (int nt = 0; nt < 8; nt++) {
                o[nt][0] *= a0; o[nt][1] *= a0;
                o[nt][2] *= a1; o[nt][3] *= a1;
            }

            // ---- stage P (tf32) into warp-private region of QP ----
            uint32_t* P = QP;   // each warp touches only rows r0..r0+15
            #pragma unroll
            for (int nt = 0; nt < 8; nt++) {
                uint2 p01 = make_uint2(f2tf(c4[nt][0]), f2tf(c4[nt][1]));
                uint2 p23 = make_uint2(f2tf(c4[nt][2]), f2tf(c4[nt][3]));
                *(uint2*)&P[(r0 + gid) * 68 + nt * 8 + tig * 2]     = p01;
                *(uint2*)&P[(r0 + gid + 8) * 68 + nt * 8 + tig * 2] = p23;
            }
            __syncwarp();

            // ---- O += P V ----
            #pragma unroll
            for (int k0 = 0; k0 < 8; k0++) {
                uint32_t a[4], bf[8][2];
                a[0] = P[(r0 + gid) * 68 + k0 * 8 + tig];
                a[1] = P[(r0 + gid + 8) * 68 + k0 * 8 + tig];
                a[2] = P[(r0 + gid) * 68 + k0 * 8 + tig + 4];
                a[3] = P[(r0 + gid + 8) * 68 + k0 * 8 + tig + 4];
                #pragma unroll
                for (int nt = 0; nt < 8; nt++) {
                    int n = nt * 8 + gid;
                    bf[nt][0] = V[(k0 * 8 + tig) * 72 + n];
                    bf[nt][1] = V[(k0 * 8 + tig + 4) * 72 + n];
                }
                #pragma unroll
                for (int nt = 0; nt < 8; nt++) mma8(o[nt], a, bf[nt]);
            }
        }

        if (jt < lastT) {
            cp_wait0();
            __syncthreads();   // all warps done with buf jt&1; loads for jt+1 done
        }
    }

    // ---- normalize and store ----
    float i0 = 1.f / l0, i1 = 1.f / l1;
    int row = b * Tt + q0 + r0 + gid;
    #pragma unroll
    for (int nt = 0; nt < 8; nt++) {
        int col = nt * 8 + tig * 2;
        *(float2*)&out[(size_t)row * Hh + col]       = make_float2(o[nt][0] * i0, o[nt][1] * i0);
        *(float2*)&out[(size_t)(row + 8) * Hh + col] = make_float2(o[nt][2] * i1, o[nt][3] * i1);
    }
}

// ---------------------------------------------------------------------------
extern "C" void kernel_launch(void* const* d_in, const int* in_sizes, int n_in,
                              void* d_out, int out_size)
{
    const float* x  = (const float*)d_in[0];
    const float* Wq = (const float*)d_in[1];
    const float* Wk = (const float*)d_in[2];
    const float* Wv = (const float*)d_in[3];
    float* out = (float*)d_out;

    static const int kQkvSmem  = (2 * 128 * 36 + 2 * 32 * 200) * (int)sizeof(uint32_t);          // 88064
    static const int kAttnSmem = (128 * 68 + 2 * 64 * 68 + 2 * 64 * 72) * (int)sizeof(uint32_t); // 106496
    cudaFuncSetAttribute(qkv_mma, cudaFuncAttributeMaxDynamicSharedMemorySize, kQkvSmem);
    cudaFuncSetAttribute(attn_flash, cudaFuncAttributeMaxDynamicSharedMemorySize, kAttnSmem);

    prep_w<<<144, 512>>>(Wq, Wk, Wv);
    qkv_mma<<<(Bb * Tt) / 128, 512, kQkvSmem>>>(x);

    dim3 grid2(Tt / 128, Bb);
    attn_flash<<<grid2, 256, kAttnSmem>>>(out);
}

// round 7
// speedup vs baseline: 3.4044x; 1.0697x over previous
#include <cuda_runtime.h>
#include <stdint.h>
#include <math.h>

#define Bb 256
#define Tt 256
#define Cc 384
#define Hh 64
#define Nqkv 192

// Scratch: projections (tf32-rounded fp32; Q pre-scaled) + fragment-ordered weights
__device__ float g_q[Bb * Tt * Hh];
__device__ float g_k[Bb * Tt * Hh];
__device__ float g_v[Bb * Tt * Hh];
__device__ float g_wt[Cc * Nqkv];   // [chunk12][ntg24][pair2][lane32][4] fragment order

__device__ __forceinline__ uint32_t f2tf(float f) {
    uint32_t u;
    asm("cvt.rna.tf32.f32 %0, %1;" : "=r"(u) : "f"(f));
    return u;
}
__device__ __forceinline__ uint32_t smaddr(const void* p) {
    return (uint32_t)__cvta_generic_to_shared(p);
}
__device__ __forceinline__ void cpa16(uint32_t d, const void* s) {
    asm volatile("cp.async.cg.shared.global [%0], [%1], 16;\n" :: "r"(d), "l"(s));
}
__device__ __forceinline__ void cp_commit() { asm volatile("cp.async.commit_group;\n"); }
__device__ __forceinline__ void cp_wait0()  { asm volatile("cp.async.wait_group 0;\n" ::: "memory"); }
__device__ __forceinline__ void cp_wait1()  { asm volatile("cp.async.wait_group 1;\n" ::: "memory"); }

__device__ __forceinline__ void mma8(float c[4], const uint32_t a[4], uint32_t b0, uint32_t b1) {
    asm volatile(
        "mma.sync.aligned.m16n8k8.row.col.f32.tf32.tf32.f32 "
        "{%0,%1,%2,%3},{%4,%5,%6,%7},{%8,%9},{%0,%1,%2,%3};\n"
        : "+f"(c[0]), "+f"(c[1]), "+f"(c[2]), "+f"(c[3])
        : "r"(a[0]), "r"(a[1]), "r"(a[2]), "r"(a[3]), "r"(b0), "r"(b1));
}

// ---------------------------------------------------------------------------
// Kernel 0: write [Wq|Wk|Wv] as tf32 in mma-B fragment order.
//   g_wt word index = (((c*24 + g)*2 + p)*32 + lane)*4 + j
//   lane=(gid,tig): j0=W[k0+tig][n], j1=W[k0+tig+4][n], j2=W[k0+8+tig][n],
//   j3=W[k0+8+tig+4][n]  with k0=c*32+p*16, n=g*8+gid.
// ---------------------------------------------------------------------------
__global__ __launch_bounds__(512) void prep_w(
    const float* __restrict__ Wq, const float* __restrict__ Wk, const float* __restrict__ Wv)
{
    int idx = blockIdx.x * 512 + threadIdx.x;       // 36 blocks -> 18432 threads
    int c    = idx / 1536;
    int rem  = idx % 1536;
    int g    = rem / 64;
    int rem2 = rem % 64;
    int p    = rem2 >> 5;
    int lane = rem2 & 31;
    int gid  = lane >> 2, tig = lane & 3;

    int n  = g * 8 + gid;
    int k0 = c * 32 + p * 16;
    const float* W = (n < 64) ? Wq : (n < 128) ? Wk : Wv;
    int nc = n & 63;

    uint4 v;
    v.x = f2tf(W[(k0 + tig) * Hh + nc]);
    v.y = f2tf(W[(k0 + tig + 4) * Hh + nc]);
    v.z = f2tf(W[(k0 + 8 + tig) * Hh + nc]);
    v.w = f2tf(W[(k0 + 8 + tig + 4) * Hh + nc]);
    *(uint4*)&g_wt[(size_t)idx * 4] = v;
}

// ---------------------------------------------------------------------------
// Kernel 1: fused QKV projection. 256 threads = 8 warps (4m x 2n),
//   warp tile 32x96, block tile 128x192, K-chunk 32, 3-stage cp.async.
// Smem: Xs 3*128*36 fp32 raw | Ws 3*6144 tf32 fragment slabs  (129 KB)
// ---------------------------------------------------------------------------
__global__ __launch_bounds__(256) void qkv_mma(const float* __restrict__ x)
{
    extern __shared__ uint32_t sm[];
    float*    Xs = (float*)sm;            // 3 * 128*36
    uint32_t* Ws = sm + 3 * 128 * 36;     // 3 * 6144

    const int tid  = threadIdx.x;
    const int lane = tid & 31;
    const int wid  = tid >> 5;
    const int gid  = lane >> 2;
    const int tig  = lane & 3;
    const int wm   = wid & 3;           // rows wm*32
    const int wn   = wid >> 2;          // cols wn*96
    const int row0 = blockIdx.x * 128;

    auto issue = [&](int ch) {
        float*    Xb = Xs + (ch % 3) * (128 * 36);
        uint32_t* Wb = Ws + (ch % 3) * 6144;
        int kk = ch * 32;
        #pragma unroll
        for (int i = 0; i < 4; i++) {
            int idx = tid + i * 256;
            int r = idx >> 3, c4 = (idx & 7) * 4;
            cpa16(smaddr(&Xb[r * 36 + c4]), &x[(size_t)(row0 + r) * Cc + kk + c4]);
        }
        #pragma unroll
        for (int i = 0; i < 6; i++) {
            int idx = tid + i * 256;
            cpa16(smaddr(&Wb[idx * 4]), &g_wt[(size_t)ch * 6144 + idx * 4]);
        }
        cp_commit();
    };

    float acc[2][12][4] = {};
    issue(0);
    issue(1);

    for (int ch = 0; ch < 12; ch++) {
        cp_wait1();
        __syncthreads();
        if (ch < 10) issue(ch + 2);

        const float*    Xb = Xs + (ch % 3) * (128 * 36);
        const uint32_t* Wb = Ws + (ch % 3) * 6144;

        #pragma unroll
        for (int p = 0; p < 2; p++) {
            // A fragments: mt 0..1, ks 0..1 (ksteps p*2, p*2+1)
            uint32_t a[2][2][4];
            #pragma unroll
            for (int mt = 0; mt < 2; mt++) {
                int r = wm * 32 + mt * 16;
                #pragma unroll
                for (int ks = 0; ks < 2; ks++) {
                    int k0 = p * 16 + ks * 8;
                    a[mt][ks][0] = f2tf(Xb[(r + gid) * 36 + k0 + tig]);
                    a[mt][ks][1] = f2tf(Xb[(r + gid + 8) * 36 + k0 + tig]);
                    a[mt][ks][2] = f2tf(Xb[(r + gid) * 36 + k0 + tig + 4]);
                    a[mt][ks][3] = f2tf(Xb[(r + gid + 8) * 36 + k0 + tig + 4]);
                }
            }
            // B in halves of 6 nt to bound register pressure
            #pragma unroll
            for (int h = 0; h < 2; h++) {
                uint4 Bv[6];
                #pragma unroll
                for (int t = 0; t < 6; t++) {
                    int ntl = h * 6 + t;
                    Bv[t] = *(const uint4*)&Wb[(((wn * 12 + ntl) * 2 + p) * 32 + lane) * 4];
                }
                #pragma unroll
                for (int mt = 0; mt < 2; mt++)
                    #pragma unroll
                    for (int t = 0; t < 6; t++) {
                        mma8(acc[mt][h * 6 + t], a[mt][0], Bv[t].x, Bv[t].y);
                        mma8(acc[mt][h * 6 + t], a[mt][1], Bv[t].z, Bv[t].w);
                    }
            }
        }
    }

    // Epilogue: tf32-round; Q pre-scaled by C^-0.5
    const float scale = rsqrtf((float)Cc);
    #pragma unroll
    for (int mt = 0; mt < 2; mt++) {
        #pragma unroll
        for (int ntl = 0; ntl < 12; ntl++) {
            int n = wn * 96 + ntl * 8 + tig * 2;
            float* outp = (n < 64) ? g_q : (n < 128) ? g_k : g_v;
            float sc = (n < 64) ? scale : 1.0f;
            int nc = n & 63;
            int r = row0 + wm * 32 + mt * 16 + gid;
            float2 v0 = make_float2(__uint_as_float(f2tf(acc[mt][ntl][0] * sc)),
                                    __uint_as_float(f2tf(acc[mt][ntl][1] * sc)));
            float2 v1 = make_float2(__uint_as_float(f2tf(acc[mt][ntl][2] * sc)),
                                    __uint_as_float(f2tf(acc[mt][ntl][3] * sc)));
            *(float2*)&outp[(size_t)r * Hh + nc] = v0;
            *(float2*)&outp[(size_t)(r + 8) * Hh + nc] = v1;
        }
    }
}

// ---------------------------------------------------------------------------
// Kernel 2: flash-attention (unchanged from R5 winner).
//   grid (2,256), 256 threads = 8 warps; warp = 16 q-rows; online softmax;
//   causal warp skipping; K/V double-buffered cp.async.
// Smem (words): QP 128*68 | K 2*64*68 | V 2*64*72 = 106496 bytes
// ---------------------------------------------------------------------------
__global__ __launch_bounds__(256, 2) void attn_flash(float* __restrict__ out)
{
    extern __shared__ uint32_t sm[];
    uint32_t* QP = sm;
    uint32_t* Kb = sm + 128 * 68;
    uint32_t* Vb = Kb + 2 * 64 * 68;

    const int tid  = threadIdx.x;
    const int lane = tid & 31;
    const int wid  = tid >> 5;
    const int gid  = lane >> 2;
    const int tig  = lane & 3;
    const int qt   = 1 - blockIdx.x;
    const int b    = blockIdx.y;
    const int q0   = qt * 128;
    const int r0   = wid * 16;
    const int lastT = 2 * qt + 1;
    const int dtile = (q0 + r0) >> 6;

    #pragma unroll
    for (int i = 0; i < 8; i++) {
        int idx = tid + i * 256;
        int r = idx >> 4, c = (idx & 15) * 4;
        cpa16(smaddr(&QP[r * 68 + c]), &g_q[(size_t)(b * Tt + q0 + r) * Hh + c]);
    }
    #pragma unroll
    for (int i = 0; i < 4; i++) {
        int idx = tid + i * 256;
        int r = idx >> 4, c = (idx & 15) * 4;
        cpa16(smaddr(&Kb[r * 68 + c]), &g_k[(size_t)(b * Tt + r) * Hh + c]);
        cpa16(smaddr(&Vb[r * 72 + c]), &g_v[(size_t)(b * Tt + r) * Hh + c]);
    }
    cp_commit();
    cp_wait0();
    __syncthreads();

    uint32_t Qa[8][4];
    #pragma unroll
    for (int k0 = 0; k0 < 8; k0++) {
        Qa[k0][0] = QP[(r0 + gid) * 68 + k0 * 8 + tig];
        Qa[k0][1] = QP[(r0 + gid + 8) * 68 + k0 * 8 + tig];
        Qa[k0][2] = QP[(r0 + gid) * 68 + k0 * 8 + tig + 4];
        Qa[k0][3] = QP[(r0 + gid + 8) * 68 + k0 * 8 + tig + 4];
    }
    __syncthreads();

    float o[8][4] = {};
    float m0 = -1e30f, m1 = -1e30f, l0 = 0.f, l1 = 0.f;

    for (int jt = 0; jt <= lastT; jt++) {
        if (jt < lastT) {
            uint32_t* Kn = Kb + ((jt + 1) & 1) * 64 * 68;
            uint32_t* Vn = Vb + ((jt + 1) & 1) * 64 * 72;
            #pragma unroll
            for (int i = 0; i < 4; i++) {
                int idx = tid + i * 256;
                int r = idx >> 4, c = (idx & 15) * 4;
                cpa16(smaddr(&Kn[r * 68 + c]), &g_k[(size_t)(b * Tt + (jt + 1) * 64 + r) * Hh + c]);
                cpa16(smaddr(&Vn[r * 72 + c]), &g_v[(size_t)(b * Tt + (jt + 1) * 64 + r) * Hh + c]);
            }
            cp_commit();
        }

        if (jt <= dtile) {
            const uint32_t* K = Kb + (jt & 1) * 64 * 68;
            const uint32_t* V = Vb + (jt & 1) * 64 * 72;

            float c4[8][4] = {};
            #pragma unroll
            for (int k0 = 0; k0 < 8; k0++) {
                uint32_t bf[8][2];
                #pragma unroll
                for (int nt = 0; nt < 8; nt++) {
                    int n = nt * 8 + gid;
                    bf[nt][0] = K[n * 68 + k0 * 8 + tig];
                    bf[nt][1] = K[n * 68 + k0 * 8 + tig + 4];
                }
                #pragma unroll
                for (int nt = 0; nt < 8; nt++) mma8(c4[nt], Qa[k0], bf[nt][0], bf[nt][1]);
            }

            if (jt == dtile) {
                int qg0 = q0 + r0 + gid, qg1 = qg0 + 8;
                #pragma unroll
                for (int nt = 0; nt < 8; nt++) {
                    int kg = jt * 64 + nt * 8 + tig * 2;
                    if (kg     > qg0) c4[nt][0] = -1e30f;
                    if (kg + 1 > qg0) c4[nt][1] = -1e30f;
                    if (kg     > qg1) c4[nt][2] = -1e30f;
                    if (kg + 1 > qg1) c4[nt][3] = -1e30f;
                }
            }

            float mx0 = -1e30f, mx1 = -1e30f;
            #pragma unroll
            for (int nt = 0; nt < 8; nt++) {
                mx0 = fmaxf(mx0, fmaxf(c4[nt][0], c4[nt][1]));
                mx1 = fmaxf(mx1, fmaxf(c4[nt][2], c4[nt][3]));
            }
            mx0 = fmaxf(mx0, __shfl_xor_sync(0xffffffffu, mx0, 1));
            mx0 = fmaxf(mx0, __shfl_xor_sync(0xffffffffu, mx0, 2));
            mx1 = fmaxf(mx1, __shfl_xor_sync(0xffffffffu, mx1, 1));
            mx1 = fmaxf(mx1, __shfl_xor_sync(0xffffffffu, mx1, 2));

            float m0n = fmaxf(m0, mx0), m1n = fmaxf(m1, mx1);
            float a0 = __expf(m0 - m0n), a1 = __expf(m1 - m1n);
            m0 = m0n; m1 = m1n;

            float s0 = 0.f, s1 = 0.f;
            #pragma unroll
            for (int nt = 0; nt < 8; nt++) {
                c4[nt][0] = __expf(c4[nt][0] - m0n);
                c4[nt][1] = __expf(c4[nt][1] - m0n);
                c4[nt][2] = __expf(c4[nt][2] - m1n);
                c4[nt][3] = __expf(c4[nt][3] - m1n);
                s0 += c4[nt][0] + c4[nt][1];
                s1 += c4[nt][2] + c4[nt][3];
            }
            s0 += __shfl_xor_sync(0xffffffffu, s0, 1);
            s0 += __shfl_xor_sync(0xffffffffu, s0, 2);
            s1 += __shfl_xor_sync(0xffffffffu, s1, 1);
            s1 += __shfl_xor_sync(0xffffffffu, s1, 2);
            l0 = l0 * a0 + s0;
            l1 = l1 * a1 + s1;

            #pragma unroll
            for (int nt = 0; nt < 8; nt++) {
                o[nt][0] *= a0; o[nt][1] *= a0;
                o[nt][2] *= a1; o[nt][3] *= a1;
            }

            uint32_t* P = QP;
            #pragma unroll
            for (int nt = 0; nt < 8; nt++) {
                uint2 p01 = make_uint2(f2tf(c4[nt][0]), f2tf(c4[nt][1]));
                uint2 p23 = make_uint2(f2tf(c4[nt][2]), f2tf(c4[nt][3]));
                *(uint2*)&P[(r0 + gid) * 68 + nt * 8 + tig * 2]     = p01;
                *(uint2*)&P[(r0 + gid + 8) * 68 + nt * 8 + tig * 2] = p23;
            }
            __syncwarp();

            #pragma unroll
            for (int k0 = 0; k0 < 8; k0++) {
                uint32_t a[4], bf[8][2];
                a[0] = P[(r0 + gid) * 68 + k0 * 8 + tig];
                a[1] = P[(r0 + gid + 8) * 68 + k0 * 8 + tig];
                a[2] = P[(r0 + gid) * 68 + k0 * 8 + tig + 4];
                a[3] = P[(r0 + gid + 8) * 68 + k0 * 8 + tig + 4];
                #pragma unroll
                for (int nt = 0; nt < 8; nt++) {
                    int n = nt * 8 + gid;
                    bf[nt][0] = V[(k0 * 8 + tig) * 72 + n];
                    bf[nt][1] = V[(k0 * 8 + tig + 4) * 72 + n];
                }
                #pragma unroll
                for (int nt = 0; nt < 8; nt++) mma8(o[nt], a, bf[nt][0], bf[nt][1]);
            }
        }

        if (jt < lastT) {
            cp_wait0();
            __syncthreads();
        }
    }

    float i0 = 1.f / l0, i1 = 1.f / l1;
    int row = b * Tt + q0 + r0 + gid;
    #pragma unroll
    for (int nt = 0; nt < 8; nt++) {
        int col = nt * 8 + tig * 2;
        *(float2*)&out[(size_t)row * Hh + col]       = make_float2(o[nt][0] * i0, o[nt][1] * i0);
        *(float2*)&out[(size_t)(row + 8) * Hh + col] = make_float2(o[nt][2] * i1, o[nt][3] * i1);
    }
}

// ---------------------------------------------------------------------------
extern "C" void kernel_launch(void* const* d_in, const int* in_sizes, int n_in,
                              void* d_out, int out_size)
{
    const float* x  = (const float*)d_in[0];
    const float* Wq = (const float*)d_in[1];
    const float* Wk = (const float*)d_in[2];
    const float* Wv = (const float*)d_in[3];
    float* out = (float*)d_out;

    static const int kQkvSmem  = (3 * 128 * 36 + 3 * 6144) * (int)sizeof(uint32_t);              // 129024
    static const int kAttnSmem = (128 * 68 + 2 * 64 * 68 + 2 * 64 * 72) * (int)sizeof(uint32_t); // 106496
    cudaFuncSetAttribute(qkv_mma, cudaFuncAttributeMaxDynamicSharedMemorySize, kQkvSmem);
    cudaFuncSetAttribute(attn_flash, cudaFuncAttributeMaxDynamicSharedMemorySize, kAttnSmem);

    prep_w<<<36, 512>>>(Wq, Wk, Wv);
    qkv_mma<<<(Bb * Tt) / 128, 256, kQkvSmem>>>(x);

    dim3 grid2(Tt / 128, Bb);
    attn_flash<<<grid2, 256, kAttnSmem>>>(out);
}

// round 8
// speedup vs baseline: 3.7298x; 1.0956x over previous
#include <cuda_runtime.h>
#include <stdint.h>
#include <math.h>

#define Bb 256
#define Tt 256
#define Cc 384
#define Hh 64
#define Nqkv 192

// Scratch: projections (tf32-rounded fp32; Q pre-scaled) + fragment-ordered weights
__device__ float g_q[Bb * Tt * Hh];
__device__ float g_k[Bb * Tt * Hh];
__device__ float g_v[Bb * Tt * Hh];
__device__ float g_wt[Cc * Nqkv];   // [chunk12][ntg24][pair2][lane32][4] fragment order

__device__ __forceinline__ uint32_t f2tf(float f) {
    uint32_t u;
    asm("cvt.rna.tf32.f32 %0, %1;" : "=r"(u) : "f"(f));
    return u;
}
__device__ __forceinline__ uint32_t smaddr(const void* p) {
    return (uint32_t)__cvta_generic_to_shared(p);
}
__device__ __forceinline__ void cpa16(uint32_t d, const void* s) {
    asm volatile("cp.async.cg.shared.global [%0], [%1], 16;\n" :: "r"(d), "l"(s));
}
__device__ __forceinline__ void cp_commit() { asm volatile("cp.async.commit_group;\n"); }
__device__ __forceinline__ void cp_wait0()  { asm volatile("cp.async.wait_group 0;\n" ::: "memory"); }

__device__ __forceinline__ void mma8(float c[4], const uint32_t a[4], uint32_t b0, uint32_t b1) {
    asm volatile(
        "mma.sync.aligned.m16n8k8.row.col.f32.tf32.tf32.f32 "
        "{%0,%1,%2,%3},{%4,%5,%6,%7},{%8,%9},{%0,%1,%2,%3};\n"
        : "+f"(c[0]), "+f"(c[1]), "+f"(c[2]), "+f"(c[3])
        : "r"(a[0]), "r"(a[1]), "r"(a[2]), "r"(a[3]), "r"(b0), "r"(b1));
}

// ---------------------------------------------------------------------------
// Kernel 0: write [Wq|Wk|Wv] as tf32 in mma-B fragment order.
//   g_wt word index = (((c*24 + g)*2 + p)*32 + lane)*4 + j
// ---------------------------------------------------------------------------
__global__ __launch_bounds__(128) void prep_w(
    const float* __restrict__ Wq, const float* __restrict__ Wk, const float* __restrict__ Wv)
{
    int idx = blockIdx.x * 128 + threadIdx.x;       // 144 blocks x 128 -> 18432
    int c    = idx / 1536;
    int rem  = idx % 1536;
    int g    = rem / 64;
    int rem2 = rem % 64;
    int p    = rem2 >> 5;
    int lane = rem2 & 31;
    int gid  = lane >> 2, tig = lane & 3;

    int n  = g * 8 + gid;
    int k0 = c * 32 + p * 16;
    const float* W = (n < 64) ? Wq : (n < 128) ? Wk : Wv;
    int nc = n & 63;

    uint4 v;
    v.x = f2tf(W[(k0 + tig) * Hh + nc]);
    v.y = f2tf(W[(k0 + tig + 4) * Hh + nc]);
    v.z = f2tf(W[(k0 + 8 + tig) * Hh + nc]);
    v.w = f2tf(W[(k0 + 8 + tig + 4) * Hh + nc]);
    *(uint4*)&g_wt[(size_t)idx * 4] = v;
}

// ---------------------------------------------------------------------------
// Kernel 1: fused QKV projection. 256 threads = 8 warps (4m x 2n),
//   warp tile 32x96, block tile 128x192, K-chunk 32, 2-stage double buffer.
// Smem: Xs 2*128*36 fp32 raw | Ws 2*6144 tf32 fragment slabs = 86016 B -> 2 CTA/SM
// ---------------------------------------------------------------------------
__global__ __launch_bounds__(256, 2) void qkv_mma(const float* __restrict__ x)
{
    extern __shared__ uint32_t sm[];
    float*    Xs = (float*)sm;            // 2 * 128*36
    uint32_t* Ws = sm + 2 * 128 * 36;     // 2 * 6144

    const int tid  = threadIdx.x;
    const int lane = tid & 31;
    const int wid  = tid >> 5;
    const int gid  = lane >> 2;
    const int tig  = lane & 3;
    const int wm   = wid & 3;           // rows wm*32
    const int wn   = wid >> 2;          // cols wn*96
    const int row0 = blockIdx.x * 128;

    auto issue = [&](int ch) {
        float*    Xb = Xs + (ch & 1) * (128 * 36);
        uint32_t* Wb = Ws + (ch & 1) * 6144;
        int kk = ch * 32;
        #pragma unroll
        for (int i = 0; i < 4; i++) {
            int idx = tid + i * 256;
            int r = idx >> 3, c4 = (idx & 7) * 4;
            cpa16(smaddr(&Xb[r * 36 + c4]), &x[(size_t)(row0 + r) * Cc + kk + c4]);
        }
        #pragma unroll
        for (int i = 0; i < 6; i++) {
            int idx = tid + i * 256;
            cpa16(smaddr(&Wb[idx * 4]), &g_wt[(size_t)ch * 6144 + idx * 4]);
        }
        cp_commit();
    };

    float acc[2][12][4] = {};
    issue(0);

    for (int ch = 0; ch < 12; ch++) {
        cp_wait0();
        __syncthreads();
        if (ch < 11) issue(ch + 1);

        const float*    Xb = Xs + (ch & 1) * (128 * 36);
        const uint32_t* Wb = Ws + (ch & 1) * 6144;

        #pragma unroll
        for (int p = 0; p < 2; p++) {
            uint32_t a[2][2][4];
            #pragma unroll
            for (int mt = 0; mt < 2; mt++) {
                int r = wm * 32 + mt * 16;
                #pragma unroll
                for (int ks = 0; ks < 2; ks++) {
                    int k0 = p * 16 + ks * 8;
                    a[mt][ks][0] = f2tf(Xb[(r + gid) * 36 + k0 + tig]);
                    a[mt][ks][1] = f2tf(Xb[(r + gid + 8) * 36 + k0 + tig]);
                    a[mt][ks][2] = f2tf(Xb[(r + gid) * 36 + k0 + tig + 4]);
                    a[mt][ks][3] = f2tf(Xb[(r + gid + 8) * 36 + k0 + tig + 4]);
                }
            }
            #pragma unroll
            for (int h = 0; h < 2; h++) {
                uint4 Bv[6];
                #pragma unroll
                for (int t = 0; t < 6; t++) {
                    int ntl = h * 6 + t;
                    Bv[t] = *(const uint4*)&Wb[(((wn * 12 + ntl) * 2 + p) * 32 + lane) * 4];
                }
                #pragma unroll
                for (int mt = 0; mt < 2; mt++)
                    #pragma unroll
                    for (int t = 0; t < 6; t++) {
                        mma8(acc[mt][h * 6 + t], a[mt][0], Bv[t].x, Bv[t].y);
                        mma8(acc[mt][h * 6 + t], a[mt][1], Bv[t].z, Bv[t].w);
                    }
            }
        }
        __syncthreads();
    }

    // Epilogue: tf32-round; Q pre-scaled by C^-0.5
    const float scale = rsqrtf((float)Cc);
    #pragma unroll
    for (int mt = 0; mt < 2; mt++) {
        #pragma unroll
        for (int ntl = 0; ntl < 12; ntl++) {
            int n = wn * 96 + ntl * 8 + tig * 2;
            float* outp = (n < 64) ? g_q : (n < 128) ? g_k : g_v;
            float sc = (n < 64) ? scale : 1.0f;
            int nc = n & 63;
            int r = row0 + wm * 32 + mt * 16 + gid;
            float2 v0 = make_float2(__uint_as_float(f2tf(acc[mt][ntl][0] * sc)),
                                    __uint_as_float(f2tf(acc[mt][ntl][1] * sc)));
            float2 v1 = make_float2(__uint_as_float(f2tf(acc[mt][ntl][2] * sc)),
                                    __uint_as_float(f2tf(acc[mt][ntl][3] * sc)));
            *(float2*)&outp[(size_t)r * Hh + nc] = v0;
            *(float2*)&outp[(size_t)(r + 8) * Hh + nc] = v1;
        }
    }
}

// ---------------------------------------------------------------------------
// Kernel 2: flash-attention (R5 winner, unchanged).
// Smem (words): QP 128*68 | K 2*64*68 | V 2*64*72 = 106496 bytes, 2 CTA/SM
// ---------------------------------------------------------------------------
__global__ __launch_bounds__(256, 2) void attn_flash(float* __restrict__ out)
{
    extern __shared__ uint32_t sm[];
    uint32_t* QP = sm;
    uint32_t* Kb = sm + 128 * 68;
    uint32_t* Vb = Kb + 2 * 64 * 68;

    const int tid  = threadIdx.x;
    const int lane = tid & 31;
    const int wid  = tid >> 5;
    const int gid  = lane >> 2;
    const int tig  = lane & 3;
    const int qt   = 1 - blockIdx.x;
    const int b    = blockIdx.y;
    const int q0   = qt * 128;
    const int r0   = wid * 16;
    const int lastT = 2 * qt + 1;
    const int dtile = (q0 + r0) >> 6;

    #pragma unroll
    for (int i = 0; i < 8; i++) {
        int idx = tid + i * 256;
        int r = idx >> 4, c = (idx & 15) * 4;
        cpa16(smaddr(&QP[r * 68 + c]), &g_q[(size_t)(b * Tt + q0 + r) * Hh + c]);
    }
    #pragma unroll
    for (int i = 0; i < 4; i++) {
        int idx = tid + i * 256;
        int r = idx >> 4, c = (idx & 15) * 4;
        cpa16(smaddr(&Kb[r * 68 + c]), &g_k[(size_t)(b * Tt + r) * Hh + c]);
        cpa16(smaddr(&Vb[r * 72 + c]), &g_v[(size_t)(b * Tt + r) * Hh + c]);
    }
    cp_commit();
    cp_wait0();
    __syncthreads();

    uint32_t Qa[8][4];
    #pragma unroll
    for (int k0 = 0; k0 < 8; k0++) {
        Qa[k0][0] = QP[(r0 + gid) * 68 + k0 * 8 + tig];
        Qa[k0][1] = QP[(r0 + gid + 8) * 68 + k0 * 8 + tig];
        Qa[k0][2] = QP[(r0 + gid) * 68 + k0 * 8 + tig + 4];
        Qa[k0][3] = QP[(r0 + gid + 8) * 68 + k0 * 8 + tig + 4];
    }
    __syncthreads();

    float o[8][4] = {};
    float m0 = -1e30f, m1 = -1e30f, l0 = 0.f, l1 = 0.f;

    for (int jt = 0; jt <= lastT; jt++) {
        if (jt < lastT) {
            uint32_t* Kn = Kb + ((jt + 1) & 1) * 64 * 68;
            uint32_t* Vn = Vb + ((jt + 1) & 1) * 64 * 72;
            #pragma unroll
            for (int i = 0; i < 4; i++) {
                int idx = tid + i * 256;
                int r = idx >> 4, c = (idx & 15) * 4;
                cpa16(smaddr(&Kn[r * 68 + c]), &g_k[(size_t)(b * Tt + (jt + 1) * 64 + r) * Hh + c]);
                cpa16(smaddr(&Vn[r * 72 + c]), &g_v[(size_t)(b * Tt + (jt + 1) * 64 + r) * Hh + c]);
            }
            cp_commit();
        }

        if (jt <= dtile) {
            const uint32_t* K = Kb + (jt & 1) * 64 * 68;
            const uint32_t* V = Vb + (jt & 1) * 64 * 72;

            float c4[8][4] = {};
            #pragma unroll
            for (int k0 = 0; k0 < 8; k0++) {
                uint32_t bf[8][2];
                #pragma unroll
                for (int nt = 0; nt < 8; nt++) {
                    int n = nt * 8 + gid;
                    bf[nt][0] = K[n * 68 + k0 * 8 + tig];
                    bf[nt][1] = K[n * 68 + k0 * 8 + tig + 4];
                }
                #pragma unroll
                for (int nt = 0; nt < 8; nt++) mma8(c4[nt], Qa[k0], bf[nt][0], bf[nt][1]);
            }

            if (jt == dtile) {
                int qg0 = q0 + r0 + gid, qg1 = qg0 + 8;
                #pragma unroll
                for (int nt = 0; nt < 8; nt++) {
                    int kg = jt * 64 + nt * 8 + tig * 2;
                    if (kg     > qg0) c4[nt][0] = -1e30f;
                    if (kg + 1 > qg0) c4[nt][1] = -1e30f;
                    if (kg     > qg1) c4[nt][2] = -1e30f;
                    if (kg + 1 > qg1) c4[nt][3] = -1e30f;
                }
            }

            float mx0 = -1e30f, mx1 = -1e30f;
            #pragma unroll
            for (int nt = 0; nt < 8; nt++) {
                mx0 = fmaxf(mx0, fmaxf(c4[nt][0], c4[nt][1]));
                mx1 = fmaxf(mx1, fmaxf(c4[nt][2], c4[nt][3]));
            }
            mx0 = fmaxf(mx0, __shfl_xor_sync(0xffffffffu, mx0, 1));
            mx0 = fmaxf(mx0, __shfl_xor_sync(0xffffffffu, mx0, 2));
            mx1 = fmaxf(mx1, __shfl_xor_sync(0xffffffffu, mx1, 1));
            mx1 = fmaxf(mx1, __shfl_xor_sync(0xffffffffu, mx1, 2));

            float m0n = fmaxf(m0, mx0), m1n = fmaxf(m1, mx1);
            float a0 = __expf(m0 - m0n), a1 = __expf(m1 - m1n);
            m0 = m0n; m1 = m1n;

            float s0 = 0.f, s1 = 0.f;
            #pragma unroll
            for (int nt = 0; nt < 8; nt++) {
                c4[nt][0] = __expf(c4[nt][0] - m0n);
                c4[nt][1] = __expf(c4[nt][1] - m0n);
                c4[nt][2] = __expf(c4[nt][2] - m1n);
                c4[nt][3] = __expf(c4[nt][3] - m1n);
                s0 += c4[nt][0] + c4[nt][1];
                s1 += c4[nt][2] + c4[nt][3];
            }
            s0 += __shfl_xor_sync(0xffffffffu, s0, 1);
            s0 += __shfl_xor_sync(0xffffffffu, s0, 2);
            s1 += __shfl_xor_sync(0xffffffffu, s1, 1);
            s1 += __shfl_xor_sync(0xffffffffu, s1, 2);
            l0 = l0 * a0 + s0;
            l1 = l1 * a1 + s1;

            #pragma unroll
            for (int nt = 0; nt < 8; nt++) {
                o[nt][0] *= a0; o[nt][1] *= a0;
                o[nt][2] *= a1; o[nt][3] *= a1;
            }

            uint32_t* P = QP;
            #pragma unroll
            for (int nt = 0; nt < 8; nt++) {
                uint2 p01 = make_uint2(f2tf(c4[nt][0]), f2tf(c4[nt][1]));
                uint2 p23 = make_uint2(f2tf(c4[nt][2]), f2tf(c4[nt][3]));
                *(uint2*)&P[(r0 + gid) * 68 + nt * 8 + tig * 2]     = p01;
                *(uint2*)&P[(r0 + gid + 8) * 68 + nt * 8 + tig * 2] = p23;
            }
            __syncwarp();

            #pragma unroll
            for (int k0 = 0; k0 < 8; k0++) {
                uint32_t a[4], bf[8][2];
                a[0] = P[(r0 + gid) * 68 + k0 * 8 + tig];
                a[1] = P[(r0 + gid + 8) * 68 + k0 * 8 + tig];
                a[2] = P[(r0 + gid) * 68 + k0 * 8 + tig + 4];
                a[3] = P[(r0 + gid + 8) * 68 + k0 * 8 + tig + 4];
                #pragma unroll
                for (int nt = 0; nt < 8; nt++) {
                    int n = nt * 8 + gid;
                    bf[nt][0] = V[(k0 * 8 + tig) * 72 + n];
                    bf[nt][1] = V[(k0 * 8 + tig + 4) * 72 + n];
                }
                #pragma unroll
                for (int nt = 0; nt < 8; nt++) mma8(o[nt], a, bf[nt][0], bf[nt][1]);
            }
        }

        if (jt < lastT) {
            cp_wait0();
            __syncthreads();
        }
    }

    float i0 = 1.f / l0, i1 = 1.f / l1;
    int row = b * Tt + q0 + r0 + gid;
    #pragma unroll
    for (int nt = 0; nt < 8; nt++) {
        int col = nt * 8 + tig * 2;
        *(float2*)&out[(size_t)row * Hh + col]       = make_float2(o[nt][0] * i0, o[nt][1] * i0);
        *(float2*)&out[(size_t)(row + 8) * Hh + col] = make_float2(o[nt][2] * i1, o[nt][3] * i1);
    }
}

// ---------------------------------------------------------------------------
extern "C" void kernel_launch(void* const* d_in, const int* in_sizes, int n_in,
                              void* d_out, int out_size)
{
    const float* x  = (const float*)d_in[0];
    const float* Wq = (const float*)d_in[1];
    const float* Wk = (const float*)d_in[2];
    const float* Wv = (const float*)d_in[3];
    float* out = (float*)d_out;

    static const int kQkvSmem  = (2 * 128 * 36 + 2 * 6144) * (int)sizeof(uint32_t);              // 86016
    static const int kAttnSmem = (128 * 68 + 2 * 64 * 68 + 2 * 64 * 72) * (int)sizeof(uint32_t); // 106496
    cudaFuncSetAttribute(qkv_mma, cudaFuncAttributeMaxDynamicSharedMemorySize, kQkvSmem);
    cudaFuncSetAttribute(attn_flash, cudaFuncAttributeMaxDynamicSharedMemorySize, kAttnSmem);

    prep_w<<<144, 128>>>(Wq, Wk, Wv);
    qkv_mma<<<(Bb * Tt) / 128, 256, kQkvSmem>>>(x);

    dim3 grid2(Tt / 128, Bb);
    attn_flash<<<grid2, 256, kAttnSmem>>>(out);
}

// round 12
// speedup vs baseline: 5.0424x; 1.3519x over previous
#include <cuda_runtime.h>
#include <cuda_fp16.h>
#include <stdint.h>
#include <math.h>

#define Bb 256
#define Tt 256
#define Cc 384
#define Hh 64

// Intermediates: fp16 projections (Q pre-scaled by C^-0.5), V also transposed.
__device__ __half  g_q[Bb * Tt * Hh];
__device__ __half  g_k[Bb * Tt * Hh];
__device__ __half  g_v[Bb * Tt * Hh];
__device__ __half  g_vT[Bb * Hh * Tt];          // [b][h][t]
__device__ uint32_t g_wt[12 * 3072];            // fp16 B-fragments: [ch][ntg24][ks2][lane32][j2]

// ---------------- helpers ----------------
__device__ __forceinline__ uint32_t pkhalf2(float lo, float hi) {
    uint32_t d;
    asm("cvt.rn.f16x2.f32 %0, %1, %2;" : "=r"(d) : "f"(hi), "f"(lo));
    return d;
}
__device__ __forceinline__ uint32_t smaddr(const void* p) {
    return (uint32_t)__cvta_generic_to_shared(p);
}
__device__ __forceinline__ void cpa16(uint32_t d, const void* s) {
    asm volatile("cp.async.cg.shared.global [%0], [%1], 16;\n" :: "r"(d), "l"(s));
}
__device__ __forceinline__ void cp_commit() { asm volatile("cp.async.commit_group;\n"); }
__device__ __forceinline__ void cp_wait0()  { asm volatile("cp.async.wait_group 0;\n" ::: "memory"); }

// m16n8k16 fp16 mma, fp32 accum
__device__ __forceinline__ void mma16(float c[4], const uint32_t a[4], uint32_t b0, uint32_t b1) {
    asm volatile(
        "mma.sync.aligned.m16n8k16.row.col.f32.f16.f16.f32 "
        "{%0,%1,%2,%3},{%4,%5,%6,%7},{%8,%9},{%0,%1,%2,%3};\n"
        : "+f"(c[0]), "+f"(c[1]), "+f"(c[2]), "+f"(c[3])
        : "r"(a[0]), "r"(a[1]), "r"(a[2]), "r"(a[3]), "r"(b0), "r"(b1));
}

// ---------------------------------------------------------------------------
// Kernel 0: weights -> fp16 B-fragments.
//   g_wt[(((ch*24+ntg)*2+ks)*32+lane)*2+j] = half2(W[k][n], W[k+1][n]),
//   n = ntg*8+gid, k = ch*32 + ks*16 + 2*tig + 8*j.
// ---------------------------------------------------------------------------
__global__ __launch_bounds__(512) void prep_w(
    const float* __restrict__ Wq, const float* __restrict__ Wk, const float* __restrict__ Wv)
{
    int idx = blockIdx.x * 512 + threadIdx.x;   // 72 blocks -> 36864
    int j    = idx & 1;
    int lane = (idx >> 1) & 31;
    int ks   = (idx >> 6) & 1;
    int t    = idx >> 7;
    int ntg  = t % 24, ch = t / 24;
    int gid  = lane >> 2, tig = lane & 3;

    int n = ntg * 8 + gid;
    const float* W = (n < 64) ? Wq : (n < 128) ? Wk : Wv;
    int nc = n & 63;
    int k  = ch * 32 + ks * 16 + 2 * tig + 8 * j;

    g_wt[idx] = pkhalf2(W[k * Hh + nc], W[(k + 1) * Hh + nc]);
}

// ---------------------------------------------------------------------------
// Kernel 1: fused QKV projection, fp16 m16n8k16.
//   256 threads = 8 warps (4m x 2n), warp tile 32x96, block 128x192,
//   K-chunk 32 (2 k16 steps), double-buffered cp.async.
// Smem: Xs 2*128*36 fp32 (raw x) | Wb 2*3072 u32 fragments = 61440 B, 2 CTA/SM
// ---------------------------------------------------------------------------
__global__ __launch_bounds__(256, 2) void qkv_mma(const float* __restrict__ x)
{
    extern __shared__ uint32_t sm[];
    float*    Xs = (float*)sm;            // 2 * 128*36
    uint32_t* Wb = sm + 2 * 128 * 36;     // 2 * 3072

    const int tid  = threadIdx.x;
    const int lane = tid & 31;
    const int wid  = tid >> 5;
    const int gid  = lane >> 2;
    const int tig  = lane & 3;
    const int wm   = wid & 3;           // rows wm*32
    const int wn   = wid >> 2;          // cols wn*96
    const int row0 = blockIdx.x * 128;

    auto issue = [&](int ch) {
        float*    Xb = Xs + (ch & 1) * (128 * 36);
        uint32_t* Bq = Wb + (ch & 1) * 3072;
        int kk = ch * 32;
        #pragma unroll
        for (int i = 0; i < 4; i++) {
            int idx = tid + i * 256;
            int r = idx >> 3, c4 = (idx & 7) * 4;
            cpa16(smaddr(&Xb[r * 36 + c4]), &x[(size_t)(row0 + r) * Cc + kk + c4]);
        }
        #pragma unroll
        for (int i = 0; i < 3; i++) {
            int idx = tid + i * 256;    // 768 granules of 16B
            cpa16(smaddr(&Bq[idx * 4]), &g_wt[(size_t)ch * 3072 + idx * 4]);
        }
        cp_commit();
    };

    float acc[2][12][4] = {};
    issue(0);

    for (int ch = 0; ch < 12; ch++) {
        cp_wait0();
        __syncthreads();
        if (ch < 11) issue(ch + 1);

        const float*    Xb = Xs + (ch & 1) * (128 * 36);
        const uint32_t* Bq = Wb + (ch & 1) * 3072;

        #pragma unroll
        for (int ks = 0; ks < 2; ks++) {
            // A fragments (fp32 -> fp16 pack in registers)
            uint32_t a[2][4];
            #pragma unroll
            for (int mt = 0; mt < 2; mt++) {
                int r = wm * 32 + mt * 16;
                float2 v0 = *(const float2*)&Xb[(r + gid) * 36 + ks * 16 + 2 * tig];
                float2 v1 = *(const float2*)&Xb[(r + gid + 8) * 36 + ks * 16 + 2 * tig];
                float2 v2 = *(const float2*)&Xb[(r + gid) * 36 + ks * 16 + 2 * tig + 8];
                float2 v3 = *(const float2*)&Xb[(r + gid + 8) * 36 + ks * 16 + 2 * tig + 8];
                a[mt][0] = pkhalf2(v0.x, v0.y);
                a[mt][1] = pkhalf2(v1.x, v1.y);
                a[mt][2] = pkhalf2(v2.x, v2.y);
                a[mt][3] = pkhalf2(v3.x, v3.y);
            }
            // B fragments, 2 halves of 6 n-tiles
            #pragma unroll
            for (int h = 0; h < 2; h++) {
                uint2 Bv[6];
                #pragma unroll
                for (int t = 0; t < 6; t++) {
                    int ntl = h * 6 + t;
                    Bv[t] = *(const uint2*)&Bq[(((wn * 12 + ntl) * 2 + ks) * 32 + lane) * 2];
                }
                #pragma unroll
                for (int mt = 0; mt < 2; mt++)
                    #pragma unroll
                    for (int t = 0; t < 6; t++)
                        mma16(acc[mt][h * 6 + t], a[mt], Bv[t].x, Bv[t].y);
            }
        }
    }

    // Epilogue: fp16 stores; Q pre-scaled by C^-0.5
    const float scale = rsqrtf((float)Cc);
    #pragma unroll
    for (int mt = 0; mt < 2; mt++) {
        #pragma unroll
        for (int ntl = 0; ntl < 12; ntl++) {
            int n = wn * 96 + ntl * 8 + tig * 2;
            __half* outp = (n < 64) ? g_q : (n < 128) ? g_k : g_v;
            float sc = (n < 64) ? scale : 1.0f;
            int ncu = (n & 63) >> 1;
            int r = row0 + wm * 32 + mt * 16 + gid;
            ((uint32_t*)outp)[r * 32 + ncu] =
                pkhalf2(acc[mt][ntl][0] * sc, acc[mt][ntl][1] * sc);
            ((uint32_t*)outp)[(r + 8) * 32 + ncu] =
                pkhalf2(acc[mt][ntl][2] * sc, acc[mt][ntl][3] * sc);
        }
    }
}

// ---------------------------------------------------------------------------
// Kernel 1b: transpose V per batch: g_v[b][t][h] -> g_vT[b][h][t].
// ---------------------------------------------------------------------------
__global__ __launch_bounds__(256) void vtrans()
{
    __shared__ __half ts[64][260];
    const int b = blockIdx.x;
    const int tid = threadIdx.x;

    #pragma unroll
    for (int i = 0; i < 32; i++) {
        int idx = tid + i * 256;          // 8192 u32 of g_v slice
        int tok = idx >> 5, hp = idx & 31;
        uint32_t v = ((const uint32_t*)g_v)[(size_t)(b * Tt + tok) * 32 + hp];
        ts[hp * 2 + 0][tok] = __ushort_as_half((unsigned short)(v & 0xFFFF));
        ts[hp * 2 + 1][tok] = __ushort_as_half((unsigned short)(v >> 16));
    }
    __syncthreads();
    #pragma unroll
    for (int i = 0; i < 32; i++) {
        int idx = tid + i * 256;
        int h = idx >> 7, tp = idx & 127;
        ((uint32_t*)g_vT)[(size_t)(b * Hh + h) * 128 + tp] = *(uint32_t*)&ts[h][tp * 2];
    }
}

// ---------------------------------------------------------------------------
// Kernel 2: flash-attention, fp16 m16n8k16, online softmax, causal warp skip.
//   grid (2,256), 256 threads = 8 warps; warp = 16 q-rows.
//   P packs directly from accumulators into A fragments (no smem staging).
// Smem (u32): Q 128*36 | K 2*64*36 | VT 2*64*36 = 13824 u32 = 55296 B
// ---------------------------------------------------------------------------
__global__ __launch_bounds__(256, 2) void attn_flash(float* __restrict__ out)
{
    extern __shared__ uint32_t sm[];
    uint32_t* Qs = sm;                 // 128*36
    uint32_t* Kb = sm + 128 * 36;      // 2 * 64*36
    uint32_t* Vb = Kb + 2 * 64 * 36;   // 2 * 64*36

    const int tid  = threadIdx.x;
    const int lane = tid & 31;
    const int wid  = tid >> 5;
    const int gid  = lane >> 2;
    const int tig  = lane & 3;
    const int qt   = 1 - blockIdx.x;    // heavy blocks first
    const int b    = blockIdx.y;
    const int q0   = qt * 128;
    const int r0   = wid * 16;
    const int lastT = 2 * qt + 1;
    const int dtile = (q0 + r0) >> 6;

    // Prologue: Q + K0 + V0
    #pragma unroll
    for (int i = 0; i < 4; i++) {
        int idx = tid + i * 256;
        int r = idx >> 3, gq = (idx & 7) * 4;
        cpa16(smaddr(&Qs[r * 36 + gq]), &g_q[(size_t)(b * Tt + q0 + r) * Hh + gq * 2]);
    }
    #pragma unroll
    for (int i = 0; i < 2; i++) {
        int idx = tid + i * 256;
        int r = idx >> 3, gq = (idx & 7) * 4;
        cpa16(smaddr(&Kb[r * 36 + gq]), &g_k[(size_t)(b * Tt + r) * Hh + gq * 2]);
        cpa16(smaddr(&Vb[r * 36 + gq]), &g_vT[(size_t)(b * Hh + r) * Tt + gq * 2]);
    }
    cp_commit();
    cp_wait0();
    __syncthreads();

    // Q fragments -> registers (16 u32)
    uint32_t Qa[4][4];
    #pragma unroll
    for (int ks = 0; ks < 4; ks++) {
        Qa[ks][0] = Qs[(r0 + gid) * 36 + 8 * ks + tig];
        Qa[ks][1] = Qs[(r0 + gid + 8) * 36 + 8 * ks + tig];
        Qa[ks][2] = Qs[(r0 + gid) * 36 + 8 * ks + tig + 4];
        Qa[ks][3] = Qs[(r0 + gid + 8) * 36 + 8 * ks + tig + 4];
    }

    float o[8][4] = {};
    float m0 = -1e30f, m1 = -1e30f, l0 = 0.f, l1 = 0.f;

    for (int jt = 0; jt <= lastT; jt++) {
        if (jt < lastT) {
            uint32_t* Kn = Kb + ((jt + 1) & 1) * (64 * 36);
            uint32_t* Vn = Vb + ((jt + 1) & 1) * (64 * 36);
            #pragma unroll
            for (int i = 0; i < 2; i++) {
                int idx = tid + i * 256;
                int r = idx >> 3, gq = (idx & 7) * 4;
                cpa16(smaddr(&Kn[r * 36 + gq]),
                      &g_k[(size_t)(b * Tt + (jt + 1) * 64 + r) * Hh + gq * 2]);
                cpa16(smaddr(&Vn[r * 36 + gq]),
                      &g_vT[(size_t)(b * Hh + r) * Tt + (jt + 1) * 64 + gq * 2]);
            }
            cp_commit();
        }

        if (jt <= dtile) {
            const uint32_t* K = Kb + (jt & 1) * (64 * 36);
            const uint32_t* V = Vb + (jt & 1) * (64 * 36);

            // ---- S = Q K^T : 16 rows x 64 keys ----
            float c4[8][4] = {};
            #pragma unroll
            for (int ks = 0; ks < 4; ks++) {
                #pragma unroll
                for (int nt = 0; nt < 8; nt++) {
                    int n = nt * 8 + gid;
                    uint32_t b0 = K[n * 36 + 8 * ks + tig];
                    uint32_t b1 = K[n * 36 + 8 * ks + tig + 4];
                    mma16(c4[nt], Qa[ks], b0, b1);
                }
            }

            if (jt == dtile) {
                int qg0 = q0 + r0 + gid, qg1 = qg0 + 8;
                #pragma unroll
                for (int nt = 0; nt < 8; nt++) {
                    int kg = jt * 64 + nt * 8 + tig * 2;
                    if (kg     > qg0) c4[nt][0] = -1e30f;
                    if (kg + 1 > qg0) c4[nt][1] = -1e30f;
                    if (kg     > qg1) c4[nt][2] = -1e30f;
                    if (kg + 1 > qg1) c4[nt][3] = -1e30f;
                }
            }

            // ---- online softmax ----
            float mx0 = -1e30f, mx1 = -1e30f;
            #pragma unroll
            for (int nt = 0; nt < 8; nt++) {
                mx0 = fmaxf(mx0, fmaxf(c4[nt][0], c4[nt][1]));
                mx1 = fmaxf(mx1, fmaxf(c4[nt][2], c4[nt][3]));
            }
            mx0 = fmaxf(mx0, __shfl_xor_sync(0xffffffffu, mx0, 1));
            mx0 = fmaxf(mx0, __shfl_xor_sync(0xffffffffu, mx0, 2));
            mx1 = fmaxf(mx1, __shfl_xor_sync(0xffffffffu, mx1, 1));
            mx1 = fmaxf(mx1, __shfl_xor_sync(0xffffffffu, mx1, 2));

            float m0n = fmaxf(m0, mx0), m1n = fmaxf(m1, mx1);
            float a0 = __expf(m0 - m0n), a1 = __expf(m1 - m1n);
            m0 = m0n; m1 = m1n;

            float s0 = 0.f, s1 = 0.f;
            #pragma unroll
            for (int nt = 0; nt < 8; nt++) {
                c4[nt][0] = __expf(c4[nt][0] - m0n);
                c4[nt][1] = __expf(c4[nt][1] - m0n);
                c4[nt][2] = __expf(c4[nt][2] - m1n);
                c4[nt][3] = __expf(c4[nt][3] - m1n);
                s0 += c4[nt][0] + c4[nt][1];
                s1 += c4[nt][2] + c4[nt][3];
            }
            s0 += __shfl_xor_sync(0xffffffffu, s0, 1);
            s0 += __shfl_xor_sync(0xffffffffu, s0, 2);
            s1 += __shfl_xor_sync(0xffffffffu, s1, 1);
            s1 += __shfl_xor_sync(0xffffffffu, s1, 2);
            l0 = l0 * a0 + s0;
            l1 = l1 * a1 + s1;

            #pragma unroll
            for (int nt = 0; nt < 8; nt++) {
                o[nt][0] *= a0; o[nt][1] *= a0;
                o[nt][2] *= a1; o[nt][3] *= a1;
            }

            // ---- O += P V : P packs straight into A fragments ----
            #pragma unroll
            for (int j = 0; j < 4; j++) {
                uint32_t a[4];
                a[0] = pkhalf2(c4[2 * j][0],     c4[2 * j][1]);
                a[1] = pkhalf2(c4[2 * j][2],     c4[2 * j][3]);
                a[2] = pkhalf2(c4[2 * j + 1][0], c4[2 * j + 1][1]);
                a[3] = pkhalf2(c4[2 * j + 1][2], c4[2 * j + 1][3]);
                #pragma unroll
                for (int nt = 0; nt < 8; nt++) {
                    int n = nt * 8 + gid;                  // h column
                    uint32_t b0 = V[n * 36 + 8 * j + tig];
                    uint32_t b1 = V[n * 36 + 8 * j + tig + 4];
                    mma16(o[nt], a, b0, b1);
                }
            }
        }

        if (jt < lastT) {
            cp_wait0();
            __syncthreads();
        }
    }

    // ---- normalize and store fp32 ----
    float i0 = 1.f / l0, i1 = 1.f / l1;
    int row = b * Tt + q0 + r0 + gid;
    #pragma unroll
    for (int nt = 0; nt < 8; nt++) {
        int col = nt * 8 + tig * 2;
        *(float2*)&out[(size_t)row * Hh + col]       = make_float2(o[nt][0] * i0, o[nt][1] * i0);
        *(float2*)&out[(size_t)(row + 8) * Hh + col] = make_float2(o[nt][2] * i1, o[nt][3] * i1);
    }
}

// ---------------------------------------------------------------------------
extern "C" void kernel_launch(void* const* d_in, const int* in_sizes, int n_in,
                              void* d_out, int out_size)
{
    const float* x  = (const float*)d_in[0];
    const float* Wq = (const float*)d_in[1];
    const float* Wk = (const float*)d_in[2];
    const float* Wv = (const float*)d_in[3];
    float* out = (float*)d_out;

    static const int kQkvSmem  = (2 * 128 * 36 + 2 * 3072) * (int)sizeof(uint32_t);   // 61440
    static const int kAttnSmem = (128 * 36 + 4 * 64 * 36) * (int)sizeof(uint32_t);    // 55296
    cudaFuncSetAttribute(qkv_mma, cudaFuncAttributeMaxDynamicSharedMemorySize, kQkvSmem);
    cudaFuncSetAttribute(attn_flash, cudaFuncAttributeMaxDynamicSharedMemorySize, kAttnSmem);

    prep_w<<<72, 512>>>(Wq, Wk, Wv);
    qkv_mma<<<(Bb * Tt) / 128, 256, kQkvSmem>>>(x);
    vtrans<<<Bb, 256>>>();

    dim3 grid2(Tt / 128, Bb);
    attn_flash<<<grid2, 256, kAttnSmem>>>(out);
}